// round 1
// baseline (speedup 1.0000x reference)
#include <cuda_runtime.h>

#define N_SPANS 1024
#define D 512
#define H 150
#define WIN 250
#define KC 16
#define NCHUNK ((WIN + KC - 1) / KC)   // 16 chunks of window positions
#define NT 160                          // 5 warps; threads 0..149 own an H column
#define OUTW (WIN + 1)

// Scratch for the factored first-layer terms (no cudaMalloc allowed).
__device__ float d_Agi[N_SPANS * H];   // g @ W1a + b1
__device__ float d_Agj[N_SPANS * H];   // g @ W1b

// ---------------------------------------------------------------------------
// Kernel A: Agi[i,h] = b1[h] + sum_d g[i,d] * W1[d,h]
//           Agj[i,h] =         sum_d g[i,d] * W1[D+d,h]
// ---------------------------------------------------------------------------
__global__ void __launch_bounds__(NT) proj_kernel(const float* __restrict__ g,
                                                  const float* __restrict__ W1,
                                                  const float* __restrict__ b1) {
    __shared__ float gs[D];
    const int i = blockIdx.x;
    const int tid = threadIdx.x;

    // cooperative load of g row
    const float4* grow = (const float4*)(g + i * D);
    for (int q = tid; q < D / 4; q += NT) ((float4*)gs)[q] = grow[q];
    __syncthreads();

    const int h = (tid < H) ? tid : (H - 1);
    float acc1 = b1[h];
    float acc2 = 0.f;
    const float* Wa = W1 + h;           // W1a: rows [0, D)
    const float* Wb = W1 + D * H + h;   // W1b: rows [D, 2D)
#pragma unroll 4
    for (int d = 0; d < D; d++) {
        const float gv = gs[d];
        acc1 = fmaf(gv, Wa[d * H], acc1);
        acc2 = fmaf(gv, Wb[d * H], acc2);
    }
    if (tid < H) {
        d_Agi[i * H + tid] = acc1;
        d_Agj[i * H + tid] = acc2;
    }
}

// ---------------------------------------------------------------------------
// Kernel B: per (i, chunk-of-16-window-positions) CTA.
//   GEMM1: h1[kk,h] = relu(Agi[i,h] + Agj[j,h] + sum_d (g_i[d]*g_j[d]) * W1c[d,h])
//   GEMM2: h2[kk,h] = relu(b2[h] + sum_d2 h1[kk,d2] * W2[d2,h])
//   s[kk]  = b3 + sum_h h2[kk,h] * W3[h]
//   out[i, k] = valid ? sm[i] + sm[j] + s : 0
// ---------------------------------------------------------------------------
__global__ void __launch_bounds__(NT) pair_kernel(const float* __restrict__ g,
                                                  const float* __restrict__ sm,
                                                  const float* __restrict__ W1,
                                                  const float* __restrict__ W2,
                                                  const float* __restrict__ b2,
                                                  const float* __restrict__ W3,
                                                  const float* __restrict__ b3,
                                                  float* __restrict__ out) {
    __shared__ float p_sm[KC][D];        // 32 KB  (also reused as reduction scratch)
    __shared__ float h1_sm[KC][152];     // 9.5 KB (padded to 152 for float4 reads)
    __shared__ float part_sm[KC][10];

    const int i = blockIdx.y;
    const int chunk = blockIdx.x;
    const int k0 = chunk * KC;
    const int kmax = min(KC, WIN - k0);  // 16, except last chunk = 10
    const int tid = threadIdx.x;

    // trailing epsilon column
    if (chunk == 0 && tid == 0) out[i * OUTW + WIN] = 0.f;

    // chunk fully out of range (largest j still < 0)?
    if (i - WIN + k0 + kmax - 1 < 0) {
        if (tid < kmax) out[i * OUTW + k0 + tid] = 0.f;
        return;
    }

    // --- stage P[kk][d] = g_i[d] * g_jc[d] (jc clipped; invalids masked later)
    const float4* gi4 = (const float4*)(g + i * D);
    for (int idx = tid; idx < KC * (D / 4); idx += NT) {
        const int kk = idx >> 7;           // / (D/4)
        const int q = idx & 127;
        const int kkc = (kk < kmax) ? kk : (kmax - 1);
        const int jc = max(i - WIN + k0 + kkc, 0);
        const float4 a = gi4[q];
        const float4 b = ((const float4*)(g + jc * D))[q];
        float4 pv;
        pv.x = a.x * b.x; pv.y = a.y * b.y; pv.z = a.z * b.z; pv.w = a.w * b.w;
        ((float4*)p_sm[kk])[q] = pv;
    }
    __syncthreads();

    const int h = (tid < H) ? tid : (H - 1);

    // --- GEMM1: 16 window positions per thread, one H column per thread
    float acc[KC];
    {
        const float agi = d_Agi[i * H + h];
#pragma unroll
        for (int kk = 0; kk < KC; kk++) {
            const int kkc = (kk < kmax) ? kk : (kmax - 1);
            const int jc = max(i - WIN + k0 + kkc, 0);
            acc[kk] = agi + d_Agj[jc * H + h];
        }
    }
    const float* Wc = W1 + 2 * D * H + h;   // W1c: rows [2D, 3D)
    for (int d = 0; d < D; d += 4) {
        const float w0 = Wc[(d + 0) * H];
        const float w1 = Wc[(d + 1) * H];
        const float w2 = Wc[(d + 2) * H];
        const float w3 = Wc[(d + 3) * H];
#pragma unroll
        for (int kk = 0; kk < KC; kk++) {
            const float4 pv = *((const float4*)&p_sm[kk][d]);
            acc[kk] = fmaf(pv.x, w0, fmaf(pv.y, w1, fmaf(pv.z, w2, fmaf(pv.w, w3, acc[kk]))));
        }
    }

    // relu -> h1 (shared), plus zero-pad columns 150..151
    if (tid < H) {
#pragma unroll
        for (int kk = 0; kk < KC; kk++) h1_sm[kk][tid] = fmaxf(acc[kk], 0.f);
    }
    for (int idx = tid; idx < KC * 2; idx += NT) h1_sm[idx >> 1][H + (idx & 1)] = 0.f;
    __syncthreads();

    // --- GEMM2
    float acc2[KC];
    {
        const float b2v = b2[h];
#pragma unroll
        for (int kk = 0; kk < KC; kk++) acc2[kk] = b2v;
    }
    const float* W2h = W2 + h;
    for (int d2 = 0; d2 < 152; d2 += 4) {
        const float w0 = (d2 + 0 < H) ? W2h[(d2 + 0) * H] : 0.f;
        const float w1 = (d2 + 1 < H) ? W2h[(d2 + 1) * H] : 0.f;
        const float w2 = (d2 + 2 < H) ? W2h[(d2 + 2) * H] : 0.f;
        const float w3 = (d2 + 3 < H) ? W2h[(d2 + 3) * H] : 0.f;
#pragma unroll
        for (int kk = 0; kk < KC; kk++) {
            const float4 hv = *((const float4*)&h1_sm[kk][d2]);
            acc2[kk] = fmaf(hv.x, w0, fmaf(hv.y, w1, fmaf(hv.z, w2, fmaf(hv.w, w3, acc2[kk]))));
        }
    }

    // --- relu -> * W3[h] -> cross-thread reduce per pair
    const float w3h = (tid < H) ? W3[tid] : 0.f;
    float* red = &p_sm[0][0];            // reuse P scratch: KC*NT = 2560 floats
#pragma unroll
    for (int kk = 0; kk < KC; kk++) {
        red[kk * NT + tid] = fmaxf(acc2[kk], 0.f) * w3h;
    }
    __syncthreads();

    {   // 160 threads = 16 pairs x 10 segments of 16
        const int kk = tid / 10;
        const int seg = tid - kk * 10;
        float ssum = 0.f;
#pragma unroll
        for (int t = 0; t < 16; t++) ssum += red[kk * NT + seg * 16 + t];
        part_sm[kk][seg] = ssum;
    }
    __syncthreads();

    if (tid < kmax) {
        float s = b3[0];
#pragma unroll
        for (int q = 0; q < 10; q++) s += part_sm[tid][q];
        const int k = k0 + tid;
        const int j = i - WIN + k;
        out[i * OUTW + k] = (j >= 0) ? (sm[i] + sm[j] + s) : 0.f;
    }
}

// ---------------------------------------------------------------------------
extern "C" void kernel_launch(void* const* d_in, const int* in_sizes, int n_in,
                              void* d_out, int out_size) {
    const float* g  = (const float*)d_in[0];
    const float* sm = (const float*)d_in[1];
    const float* W1 = (const float*)d_in[2];
    const float* b1 = (const float*)d_in[3];
    const float* W2 = (const float*)d_in[4];
    const float* b2 = (const float*)d_in[5];
    const float* W3 = (const float*)d_in[6];
    const float* b3 = (const float*)d_in[7];
    float* out = (float*)d_out;

    proj_kernel<<<N_SPANS, NT>>>(g, W1, b1);
    dim3 grid(NCHUNK, N_SPANS);
    pair_kernel<<<grid, NT>>>(g, sm, W1, W2, b2, W3, b3, out);
}

// round 4
// speedup vs baseline: 2.9690x; 2.9690x over previous
#include <cuda_runtime.h>
#include <cstdint>

#define N_SPANS 1024
#define D 512
#define H 150
#define HP 160
#define WIN 250
#define OUTW (WIN + 1)
#define NT 256

// strides (floats) with bank-conflict padding
#define STA 68     // A-stage row stride (64 data + 4 pad)
#define STH 164    // h1 row stride (160 data + 4 pad)

// SMEM float offsets
#define OF_H1   0                      // 128*164 = 20992
#define OF_A    20992                  // 128*68  = 8704
#define OF_B    29696                  // 160*68  = 10880
#define OF_GI   40576                  // 512
#define OF_B2   41088                  // 160
#define OF_W3   41248                  // 160
#define OF_SRED 41408                  // 256
#define SMEM_FLOATS 41664
#define SMEM_BYTES (SMEM_FLOATS * 4)   // 166,656 B

// ---------------- device scratch -------------------------------------------
__device__ __align__(16) float d_Agi[N_SPANS * HP];   // g@W1a + b1 (padded)
__device__ __align__(16) float d_Agj[N_SPANS * HP];   // g@W1b      (padded)
__device__ __align__(16) float d_B1t[HP * D];         // W1c^T [n][k], tf32-rounded
__device__ __align__(16) float d_B2t[HP * HP];        // W2^T  [n][k2], tf32-rounded

// ---------------- helpers ---------------------------------------------------
__device__ __forceinline__ uint32_t to_tf32(float x) {
    uint32_t r;
    asm("cvt.rna.tf32.f32 %0, %1;" : "=r"(r) : "f"(x));
    return r;
}
__device__ __forceinline__ void mma_tf32(float* c, const uint32_t* a, const uint32_t* b) {
    asm volatile(
        "mma.sync.aligned.m16n8k8.row.col.f32.tf32.tf32.f32 "
        "{%0,%1,%2,%3}, {%4,%5,%6,%7}, {%8,%9}, {%0,%1,%2,%3};"
        : "+f"(c[0]), "+f"(c[1]), "+f"(c[2]), "+f"(c[3])
        : "r"(a[0]), "r"(a[1]), "r"(a[2]), "r"(a[3]), "r"(b[0]), "r"(b[1]));
}

// ---------------------------------------------------------------------------
// Prep kernels
// ---------------------------------------------------------------------------
__global__ void __launch_bounds__(160) proj_kernel(const float* __restrict__ g,
                                                   const float* __restrict__ W1,
                                                   const float* __restrict__ b1) {
    __shared__ float gs[D];
    const int i = blockIdx.x, tid = threadIdx.x;
    const float4* grow = (const float4*)(g + i * D);
    for (int q = tid; q < D / 4; q += 160) ((float4*)gs)[q] = grow[q];
    __syncthreads();
    const int h = (tid < H) ? tid : (H - 1);
    float a1 = b1[h], a2 = 0.f;
    const float* Wa = W1 + h;
    const float* Wb = W1 + D * H + h;
#pragma unroll 4
    for (int d = 0; d < D; d++) {
        const float gv = gs[d];
        a1 = fmaf(gv, Wa[d * H], a1);
        a2 = fmaf(gv, Wb[d * H], a2);
    }
    if (tid < HP) {
        d_Agi[i * HP + tid] = (tid < H) ? a1 : 0.f;
        d_Agj[i * HP + tid] = (tid < H) ? a2 : 0.f;
    }
}

__global__ void __launch_bounds__(512) prepB1t_kernel(const float* __restrict__ W1) {
    const int n = blockIdx.x;               // 0..159
    for (int k = threadIdx.x; k < D; k += 512) {
        const float v = (n < H) ? W1[(2 * D + k) * H + n] : 0.f;
        d_B1t[n * D + k] = __uint_as_float(to_tf32(v));
    }
}
__global__ void __launch_bounds__(160) prepB2t_kernel(const float* __restrict__ W2) {
    const int n = blockIdx.x;               // 0..159
    const int k = threadIdx.x;              // 0..159
    const float v = (n < H && k < H) ? W2[k * H + n] : 0.f;
    d_B2t[n * HP + k] = __uint_as_float(to_tf32(v));
}

// ---------------------------------------------------------------------------
// Main fused kernel: CTA = (span i, window half). M=128, N=160, K=512.
// 8 warps: warp_m = w%4 (32 rows), warp_n = w/4 (80 cols -> 10 n8 atoms).
// ---------------------------------------------------------------------------
__global__ void __launch_bounds__(NT, 1) pair_mma_kernel(const float* __restrict__ g,
                                                         const float* __restrict__ sm,
                                                         const float* __restrict__ W3,
                                                         const float* __restrict__ b2,
                                                         const float* __restrict__ b3,
                                                         float* __restrict__ out) {
    extern __shared__ float smf[];
    float* sH1 = smf + OF_H1;
    float* sA  = smf + OF_A;
    float* sB  = smf + OF_B;
    float* sGI = smf + OF_GI;
    float* sB2 = smf + OF_B2;
    float* sW3 = smf + OF_W3;
    float* sRD = smf + OF_SRED;

    const int tid = threadIdx.x;
    const int lane = tid & 31;
    const int w = tid >> 5;
    const int gq = lane >> 2;      // groupID 0..7
    const int tg = lane & 3;       // threadID_in_group 0..3
    const int warp_m = w & 3;
    const int warp_n = w >> 2;

    const int i = blockIdx.x >> 1;
    const int kbase = (blockIdx.x & 1) * 128;

    // ---- stage gi, b2, w3
    {
        const float4* gi4 = (const float4*)(g + i * D);
        for (int q = tid; q < D / 4; q += NT) ((float4*)sGI)[q] = gi4[q];
        for (int x = tid; x < HP; x += NT) {
            sB2[x] = (x < H) ? b2[x] : 0.f;
            sW3[x] = (x < H) ? W3[x] : 0.f;
        }
    }
    // ---- h1pre[m][c] = Agi[i][c] + Agj[jc(m)][c]
    for (int x = tid; x < 128 * (HP / 4); x += NT) {
        const int m = x / (HP / 4), q = x % (HP / 4);
        const int jc = min(max(i - WIN + kbase + m, 0), N_SPANS - 1);
        const float4 aj = ((const float4*)(d_Agj + jc * HP))[q];
        const float4 ai = ((const float4*)(d_Agi + i * HP))[q];
        float4 v;
        v.x = ai.x + aj.x; v.y = ai.y + aj.y; v.z = ai.z + aj.z; v.w = ai.w + aj.w;
        *(float4*)(sH1 + m * STH + q * 4) = v;
    }
    __syncthreads();

    float acc[2][10][4];
#pragma unroll
    for (int ma = 0; ma < 2; ma++)
#pragma unroll
        for (int na = 0; na < 10; na++)
#pragma unroll
            for (int q = 0; q < 4; q++) acc[ma][na][q] = 0.f;

    // =================== GEMM1: P[128x512] @ W1c^T -> acc ===================
    for (int ch = 0; ch < 8; ch++) {
        const int kc0 = ch * 64;
        // A fill: P[m][kk] = tf32(gi[kc0+kk] * gj[m][kc0+kk]); 16 f4 per row
        for (int x = tid; x < 128 * 16; x += NT) {
            const int m = x >> 4, q = x & 15;
            const int jc = min(max(i - WIN + kbase + m, 0), N_SPANS - 1);
            const float4 a = ((const float4*)sGI)[kc0 / 4 + q];
            const float4 b = ((const float4*)(g + jc * D + kc0))[q];
            uint4 p;
            p.x = to_tf32(a.x * b.x); p.y = to_tf32(a.y * b.y);
            p.z = to_tf32(a.z * b.z); p.w = to_tf32(a.w * b.w);
            *(uint4*)(sA + m * STA + q * 4) = p;
        }
        // B fill: 160 rows x 16 f4
        for (int x = tid; x < HP * 16; x += NT) {
            const int n = x >> 4, q = x & 15;
            *(float4*)(sB + n * STA + q * 4) =
                ((const float4*)(d_B1t + n * D + kc0))[q];
        }
        __syncthreads();
#pragma unroll
        for (int ks = 0; ks < 8; ks++) {
            const int k8 = ks * 8;
            uint32_t a[2][4];
#pragma unroll
            for (int ma = 0; ma < 2; ma++) {
                const float* p = sA + (warp_m * 32 + ma * 16 + gq) * STA + k8 + tg;
                a[ma][0] = __float_as_uint(p[0]);
                a[ma][1] = __float_as_uint(p[8 * STA]);
                a[ma][2] = __float_as_uint(p[4]);
                a[ma][3] = __float_as_uint(p[8 * STA + 4]);
            }
            uint32_t b[10][2];
#pragma unroll
            for (int na = 0; na < 10; na++) {
                const float* p = sB + (warp_n * 80 + na * 8 + gq) * STA + k8 + tg;
                b[na][0] = __float_as_uint(p[0]);
                b[na][1] = __float_as_uint(p[4]);
            }
#pragma unroll
            for (int ma = 0; ma < 2; ma++)
#pragma unroll
                for (int na = 0; na < 10; na++) mma_tf32(acc[ma][na], a[ma], b[na]);
        }
        __syncthreads();
    }

    // ====== Epilogue 1: h1 = tf32(relu(acc + h1pre)), written in place ======
#pragma unroll
    for (int ma = 0; ma < 2; ma++) {
        const int r0 = warp_m * 32 + ma * 16 + gq;
#pragma unroll
        for (int na = 0; na < 10; na++) {
            const int c0 = warp_n * 80 + na * 8 + tg * 2;
            float2 pre0 = *(const float2*)(sH1 + r0 * STH + c0);
            float2 pre1 = *(const float2*)(sH1 + (r0 + 8) * STH + c0);
            float2 o0, o1;
            o0.x = __uint_as_float(to_tf32(fmaxf(acc[ma][na][0] + pre0.x, 0.f)));
            o0.y = __uint_as_float(to_tf32(fmaxf(acc[ma][na][1] + pre0.y, 0.f)));
            o1.x = __uint_as_float(to_tf32(fmaxf(acc[ma][na][2] + pre1.x, 0.f)));
            o1.y = __uint_as_float(to_tf32(fmaxf(acc[ma][na][3] + pre1.y, 0.f)));
            *(float2*)(sH1 + r0 * STH + c0) = o0;
            *(float2*)(sH1 + (r0 + 8) * STH + c0) = o1;
        }
    }
    __syncthreads();

    // =================== GEMM2: h1[128x160] @ W2^T -> acc ===================
#pragma unroll
    for (int ma = 0; ma < 2; ma++)
#pragma unroll
        for (int na = 0; na < 10; na++)
#pragma unroll
            for (int q = 0; q < 4; q++) acc[ma][na][q] = 0.f;

    for (int ch = 0; ch < 3; ch++) {
        const int kc0 = ch * 64;
        const int ksz = (ch < 2) ? 64 : 32;
        const int nf4 = ksz / 4;
        for (int x = tid; x < HP * nf4; x += NT) {
            const int n = x / nf4, q = x % nf4;
            *(float4*)(sB + n * STA + q * 4) =
                ((const float4*)(d_B2t + n * HP + kc0))[q];
        }
        __syncthreads();
        const int nks = ksz / 8;
        for (int ks = 0; ks < nks; ks++) {
            const int k8 = ks * 8;
            uint32_t a[2][4];
#pragma unroll
            for (int ma = 0; ma < 2; ma++) {
                const float* p = sH1 + (warp_m * 32 + ma * 16 + gq) * STH + kc0 + k8 + tg;
                a[ma][0] = __float_as_uint(p[0]);
                a[ma][1] = __float_as_uint(p[8 * STH]);
                a[ma][2] = __float_as_uint(p[4]);
                a[ma][3] = __float_as_uint(p[8 * STH + 4]);
            }
            uint32_t b[10][2];
#pragma unroll
            for (int na = 0; na < 10; na++) {
                const float* p = sB + (warp_n * 80 + na * 8 + gq) * STA + k8 + tg;
                b[na][0] = __float_as_uint(p[0]);
                b[na][1] = __float_as_uint(p[4]);
            }
#pragma unroll
            for (int ma = 0; ma < 2; ma++)
#pragma unroll
                for (int na = 0; na < 10; na++) mma_tf32(acc[ma][na], a[ma], b[na]);
        }
        __syncthreads();
    }

    // ====== Epilogue 2: s[m] = sum_h relu(acc + b2[h]) * W3[h] ==============
    float part[4] = {0.f, 0.f, 0.f, 0.f};   // rows gq, gq+8, gq+16, gq+24 (+warp_m*32)
#pragma unroll
    for (int ma = 0; ma < 2; ma++) {
#pragma unroll
        for (int na = 0; na < 10; na++) {
            const int c0 = warp_n * 80 + na * 8 + tg * 2;
            const float2 bb = *(const float2*)(sB2 + c0);
            const float2 ww = *(const float2*)(sW3 + c0);
            part[ma * 2 + 0] += fmaxf(acc[ma][na][0] + bb.x, 0.f) * ww.x
                              + fmaxf(acc[ma][na][1] + bb.y, 0.f) * ww.y;
            part[ma * 2 + 1] += fmaxf(acc[ma][na][2] + bb.x, 0.f) * ww.x
                              + fmaxf(acc[ma][na][3] + bb.y, 0.f) * ww.y;
        }
    }
#pragma unroll
    for (int q = 0; q < 4; q++) {
        part[q] += __shfl_xor_sync(0xffffffffu, part[q], 1);
        part[q] += __shfl_xor_sync(0xffffffffu, part[q], 2);
    }
    if (tg == 0) {
        const int r0 = warp_m * 32 + gq;
        sRD[warp_n * 128 + r0 +  0] = part[0];
        sRD[warp_n * 128 + r0 +  8] = part[1];
        sRD[warp_n * 128 + r0 + 16] = part[2];
        sRD[warp_n * 128 + r0 + 24] = part[3];
    }
    __syncthreads();

    if (tid < 128) {
        const int m = tid;
        const int k = kbase + m;
        const float s = sRD[m] + sRD[128 + m] + b3[0];
        if (k < WIN) {
            const int j = i - WIN + k;
            out[i * OUTW + k] = (j >= 0) ? (sm[i] + sm[j] + s) : 0.f;
        } else if (k == WIN) {
            out[i * OUTW + WIN] = 0.f;   // trailing epsilon column
        }
    }
}

// ---------------------------------------------------------------------------
extern "C" void kernel_launch(void* const* d_in, const int* in_sizes, int n_in,
                              void* d_out, int out_size) {
    const float* g  = (const float*)d_in[0];
    const float* sm = (const float*)d_in[1];
    const float* W1 = (const float*)d_in[2];
    const float* b1 = (const float*)d_in[3];
    const float* W2 = (const float*)d_in[4];
    const float* b2 = (const float*)d_in[5];
    const float* W3 = (const float*)d_in[6];
    const float* b3 = (const float*)d_in[7];
    float* out = (float*)d_out;

    cudaFuncSetAttribute(pair_mma_kernel, cudaFuncAttributeMaxDynamicSharedMemorySize,
                         SMEM_BYTES);

    proj_kernel<<<N_SPANS, 160>>>(g, W1, b1);
    prepB1t_kernel<<<HP, 512>>>(W1);
    prepB2t_kernel<<<HP, 160>>>(W2);
    pair_mma_kernel<<<2 * N_SPANS, NT, SMEM_BYTES>>>(g, sm, W3, b2, b3, out);
}

// round 5
// speedup vs baseline: 3.4468x; 1.1609x over previous
#include <cuda_runtime.h>
#include <cstdint>

#define N_SPANS 1024
#define D 512
#define H 150
#define HP 160
#define WIN 250
#define OUTW (WIN + 1)
#define NT 256
#define KC 32

// strides (floats): 4 mod 32 stagger -> conflict-free ldmatrix/STS
#define STA 36     // stage row stride (32 data + 4 pad)
#define STH 164    // h1 row stride (160 data + 4 pad)

// SMEM float offsets
#define OF_H1   0                       // 128*164 = 20992
#define OF_A0   20992                   // 128*36  = 4608
#define OF_A1   25600
#define OF_B0   30208                   // 160*36  = 5760
#define OF_B1   35968
#define OF_GI   41728                   // 512
#define OF_B2   42240                   // 160
#define OF_W3   42400                   // 160
#define OF_SRED 42560                   // 256
#define SMEM_FLOATS 42816
#define SMEM_BYTES (SMEM_FLOATS * 4)    // 171,264 B

// ---------------- device scratch -------------------------------------------
__device__ __align__(16) float d_Agi[N_SPANS * HP];
__device__ __align__(16) float d_Agj[N_SPANS * HP];
__device__ __align__(16) float d_B1t[HP * D];      // W1c^T [n][k], tf32
__device__ __align__(16) float d_B2t[HP * HP];     // W2^T  [n][k2], tf32

// ---------------- helpers ---------------------------------------------------
__device__ __forceinline__ uint32_t to_tf32(float x) {
    uint32_t r;
    asm("cvt.rna.tf32.f32 %0, %1;" : "=r"(r) : "f"(x));
    return r;
}
__device__ __forceinline__ uint32_t smem_u32(const void* p) {
    uint32_t a;
    asm("{ .reg .u64 t; cvta.to.shared.u64 t, %1; cvt.u32.u64 %0, t; }" : "=r"(a) : "l"(p));
    return a;
}
__device__ __forceinline__ void mma_tf32(float* c, const uint32_t* a, const uint32_t* b) {
    asm volatile(
        "mma.sync.aligned.m16n8k8.row.col.f32.tf32.tf32.f32 "
        "{%0,%1,%2,%3}, {%4,%5,%6,%7}, {%8,%9}, {%0,%1,%2,%3};"
        : "+f"(c[0]), "+f"(c[1]), "+f"(c[2]), "+f"(c[3])
        : "r"(a[0]), "r"(a[1]), "r"(a[2]), "r"(a[3]), "r"(b[0]), "r"(b[1]));
}
__device__ __forceinline__ void ldm_x4(uint32_t* r, uint32_t saddr) {
    asm volatile("ldmatrix.sync.aligned.m8n8.x4.shared.b16 {%0,%1,%2,%3}, [%4];"
                 : "=r"(r[0]), "=r"(r[1]), "=r"(r[2]), "=r"(r[3]) : "r"(saddr));
}

// ---------------------------------------------------------------------------
// Prep kernels
// ---------------------------------------------------------------------------
__global__ void __launch_bounds__(160) proj_kernel(const float* __restrict__ g,
                                                   const float* __restrict__ W1,
                                                   const float* __restrict__ b1) {
    __shared__ float gs[D];
    const int i = blockIdx.x, tid = threadIdx.x;
    const float4* grow = (const float4*)(g + i * D);
    for (int q = tid; q < D / 4; q += 160) ((float4*)gs)[q] = grow[q];
    __syncthreads();
    const int h = (tid < H) ? tid : (H - 1);
    float a1 = b1[h], a2 = 0.f;
    const float* Wa = W1 + h;
    const float* Wb = W1 + D * H + h;
#pragma unroll 4
    for (int d = 0; d < D; d++) {
        const float gv = gs[d];
        a1 = fmaf(gv, Wa[d * H], a1);
        a2 = fmaf(gv, Wb[d * H], a2);
    }
    if (tid < HP) {
        d_Agi[i * HP + tid] = (tid < H) ? a1 : 0.f;
        d_Agj[i * HP + tid] = (tid < H) ? a2 : 0.f;
    }
}
__global__ void __launch_bounds__(512) prepB1t_kernel(const float* __restrict__ W1) {
    const int n = blockIdx.x;
    for (int k = threadIdx.x; k < D; k += 512) {
        const float v = (n < H) ? W1[(2 * D + k) * H + n] : 0.f;
        d_B1t[n * D + k] = __uint_as_float(to_tf32(v));
    }
}
__global__ void __launch_bounds__(160) prepB2t_kernel(const float* __restrict__ W2) {
    const int n = blockIdx.x, k = threadIdx.x;
    const float v = (n < H && k < H) ? W2[k * H + n] : 0.f;
    d_B2t[n * HP + k] = __uint_as_float(to_tf32(v));
}

// ---------------------------------------------------------------------------
// Main fused kernel
// ---------------------------------------------------------------------------
__global__ void __launch_bounds__(NT, 1) pair_mma_kernel(const float* __restrict__ g,
                                                         const float* __restrict__ sm,
                                                         const float* __restrict__ W3,
                                                         const float* __restrict__ b2,
                                                         const float* __restrict__ b3,
                                                         float* __restrict__ out) {
    extern __shared__ float smf[];
    float* sH1 = smf + OF_H1;
    float* sGI = smf + OF_GI;
    float* sB2 = smf + OF_B2;
    float* sW3 = smf + OF_W3;
    float* sRD = smf + OF_SRED;
    const uint32_t smb = smem_u32(smf);

    const int tid = threadIdx.x;
    const int lane = tid & 31;
    const int w = tid >> 5;
    const int tg = lane & 3;
    const int warp_m = w & 3;
    const int warp_n = w >> 2;

    const int i = blockIdx.x >> 1;
    const int kbase = (blockIdx.x & 1) * 128;

    // ldmatrix per-lane tile offsets
    const int rowA = (lane & 7) + ((lane >> 3) & 1) * 8;
    const int colA = ((lane >> 4) & 1) * 4;
    const int rowB = (lane & 7) + ((lane >> 4) & 1) * 8;
    const int colB = ((lane >> 3) & 1) * 4;

    const int OFA[2] = {OF_A0, OF_A1};
    const int OFB[2] = {OF_B0, OF_B1};

    // ---- stage gi, b2, w3
    {
        const float4* gi4 = (const float4*)(g + i * D);
        for (int q = tid; q < D / 4; q += NT) ((float4*)sGI)[q] = gi4[q];
        for (int x = tid; x < HP; x += NT) {
            sB2[x] = (x < H) ? b2[x] : 0.f;
            sW3[x] = (x < H) ? W3[x] : 0.f;
        }
    }
    // ---- h1pre[m][c] = Agi[i][c] + Agj[jc(m)][c]
    for (int x = tid; x < 128 * (HP / 4); x += NT) {
        const int m = x / (HP / 4), q = x % (HP / 4);
        const int jc = min(max(i - WIN + kbase + m, 0), N_SPANS - 1);
        const float4 aj = ((const float4*)(d_Agj + jc * HP))[q];
        const float4 ai = ((const float4*)(d_Agi + i * HP))[q];
        float4 v;
        v.x = ai.x + aj.x; v.y = ai.y + aj.y; v.z = ai.z + aj.z; v.w = ai.w + aj.w;
        *(float4*)(sH1 + m * STH + q * 4) = v;
    }

    float acc[2][10][4];
#pragma unroll
    for (int ma = 0; ma < 2; ma++)
#pragma unroll
        for (int na = 0; na < 10; na++)
#pragma unroll
            for (int q = 0; q < 4; q++) acc[ma][na][q] = 0.f;

    float4 pgj[4];   // A prefetch (gj raw)
    float4 pb[5];    // B prefetch

    // prefetch helpers (manually inlined via lambdas)
    auto ldA = [&](int kc0) {
#pragma unroll
        for (int it = 0; it < 4; it++) {
            const int x = tid + it * NT;
            const int m = x >> 3, q = x & 7;
            const int jc = min(max(i - WIN + kbase + m, 0), N_SPANS - 1);
            pgj[it] = ((const float4*)(g + jc * D + kc0))[q];
        }
    };
    auto stA = [&](int buf, int kc0) {
        float* bA = smf + OFA[buf];
#pragma unroll
        for (int it = 0; it < 4; it++) {
            const int x = tid + it * NT;
            const int m = x >> 3, q = x & 7;
            const float4 a = ((const float4*)sGI)[(kc0 >> 2) + q];
            uint4 p;
            p.x = to_tf32(a.x * pgj[it].x); p.y = to_tf32(a.y * pgj[it].y);
            p.z = to_tf32(a.z * pgj[it].z); p.w = to_tf32(a.w * pgj[it].w);
            *(uint4*)(bA + m * STA + q * 4) = p;
        }
    };
    auto ldB = [&](const float* Bsrc, int ldb, int kc0) {
#pragma unroll
        for (int it = 0; it < 5; it++) {
            const int x = tid + it * NT;
            const int n = x >> 3, q = x & 7;
            pb[it] = ((const float4*)(Bsrc + n * ldb + kc0))[q];
        }
    };
    auto stB = [&](int buf) {
        float* bB = smf + OFB[buf];
#pragma unroll
        for (int it = 0; it < 5; it++) {
            const int x = tid + it * NT;
            const int n = x >> 3, q = x & 7;
            *(float4*)(bB + n * STA + q * 4) = pb[it];
        }
    };
    auto mma_chunk_staged = [&](int buf) {   // A from stage buf, B from stage buf
#pragma unroll
        for (int ks = 0; ks < 4; ks++) {
            const int k8 = ks * 8;
            uint32_t a[2][4];
#pragma unroll
            for (int ma = 0; ma < 2; ma++)
                ldm_x4(a[ma], smb + (uint32_t)(OFA[buf] + (warp_m * 32 + ma * 16 + rowA) * STA + k8 + colA) * 4);
            uint32_t b[5][4];
#pragma unroll
            for (int pr = 0; pr < 5; pr++)
                ldm_x4(b[pr], smb + (uint32_t)(OFB[buf] + (warp_n * 80 + pr * 16 + rowB) * STA + k8 + colB) * 4);
#pragma unroll
            for (int ma = 0; ma < 2; ma++)
#pragma unroll
                for (int pr = 0; pr < 5; pr++) {
                    mma_tf32(acc[ma][pr * 2 + 0], a[ma], &b[pr][0]);
                    mma_tf32(acc[ma][pr * 2 + 1], a[ma], &b[pr][2]);
                }
        }
    };

    // =================== GEMM1: 16 pipelined chunks =========================
    ldA(0); ldB(d_B1t, D, 0);
    stA(0, 0); stB(0);
    __syncthreads();
#pragma unroll 1
    for (int ch = 0; ch < 16; ch++) {
        const int cur = ch & 1, nxt = cur ^ 1;
        if (ch < 15) { ldA((ch + 1) * KC); ldB(d_B1t, D, (ch + 1) * KC); }
        mma_chunk_staged(cur);
        if (ch < 15) { stA(nxt, (ch + 1) * KC); stB(nxt); }
        __syncthreads();
    }

    // ====== Epilogue 1: h1 = tf32(relu(acc + h1pre)) in place ===============
    const int gq = lane >> 2;
#pragma unroll
    for (int ma = 0; ma < 2; ma++) {
        const int r0 = warp_m * 32 + ma * 16 + gq;
#pragma unroll
        for (int na = 0; na < 10; na++) {
            const int c0 = warp_n * 80 + na * 8 + tg * 2;
            float2 pre0 = *(const float2*)(sH1 + r0 * STH + c0);
            float2 pre1 = *(const float2*)(sH1 + (r0 + 8) * STH + c0);
            float2 o0, o1;
            o0.x = __uint_as_float(to_tf32(fmaxf(acc[ma][na][0] + pre0.x, 0.f)));
            o0.y = __uint_as_float(to_tf32(fmaxf(acc[ma][na][1] + pre0.y, 0.f)));
            o1.x = __uint_as_float(to_tf32(fmaxf(acc[ma][na][2] + pre1.x, 0.f)));
            o1.y = __uint_as_float(to_tf32(fmaxf(acc[ma][na][3] + pre1.y, 0.f)));
            *(float2*)(sH1 + r0 * STH + c0) = o0;
            *(float2*)(sH1 + (r0 + 8) * STH + c0) = o1;
        }
    }

    // reset acc
#pragma unroll
    for (int ma = 0; ma < 2; ma++)
#pragma unroll
        for (int na = 0; na < 10; na++)
#pragma unroll
            for (int q = 0; q < 4; q++) acc[ma][na][q] = 0.f;

    // =================== GEMM2: 5 pipelined chunks (A = sH1) ================
    ldB(d_B2t, HP, 0);
    stB(0);
    __syncthreads();   // also publishes epilogue-1 h1 writes
#pragma unroll 1
    for (int ch = 0; ch < 5; ch++) {
        const int cur = ch & 1, nxt = cur ^ 1;
        if (ch < 4) ldB(d_B2t, HP, (ch + 1) * KC);
        {
            const int kc0 = ch * KC;
#pragma unroll
            for (int ks = 0; ks < 4; ks++) {
                const int k8 = ks * 8;
                uint32_t a[2][4];
#pragma unroll
                for (int ma = 0; ma < 2; ma++)
                    ldm_x4(a[ma], smb + (uint32_t)(OF_H1 + (warp_m * 32 + ma * 16 + rowA) * STH + kc0 + k8 + colA) * 4);
                uint32_t b[5][4];
#pragma unroll
                for (int pr = 0; pr < 5; pr++)
                    ldm_x4(b[pr], smb + (uint32_t)(OFB[cur] + (warp_n * 80 + pr * 16 + rowB) * STA + k8 + colB) * 4);
#pragma unroll
                for (int ma = 0; ma < 2; ma++)
#pragma unroll
                    for (int pr = 0; pr < 5; pr++) {
                        mma_tf32(acc[ma][pr * 2 + 0], a[ma], &b[pr][0]);
                        mma_tf32(acc[ma][pr * 2 + 1], a[ma], &b[pr][2]);
                    }
            }
        }
        if (ch < 4) stB(nxt);
        __syncthreads();
    }

    // ====== Epilogue 2: s[m] = sum_h relu(acc + b2[h]) * W3[h] ==============
    float part[4] = {0.f, 0.f, 0.f, 0.f};
#pragma unroll
    for (int ma = 0; ma < 2; ma++) {
#pragma unroll
        for (int na = 0; na < 10; na++) {
            const int c0 = warp_n * 80 + na * 8 + tg * 2;
            const float2 bb = *(const float2*)(sB2 + c0);
            const float2 ww = *(const float2*)(sW3 + c0);
            part[ma * 2 + 0] += fmaxf(acc[ma][na][0] + bb.x, 0.f) * ww.x
                              + fmaxf(acc[ma][na][1] + bb.y, 0.f) * ww.y;
            part[ma * 2 + 1] += fmaxf(acc[ma][na][2] + bb.x, 0.f) * ww.x
                              + fmaxf(acc[ma][na][3] + bb.y, 0.f) * ww.y;
        }
    }
#pragma unroll
    for (int q = 0; q < 4; q++) {
        part[q] += __shfl_xor_sync(0xffffffffu, part[q], 1);
        part[q] += __shfl_xor_sync(0xffffffffu, part[q], 2);
    }
    if (tg == 0) {
        const int r0 = warp_m * 32 + gq;
        sRD[warp_n * 128 + r0 +  0] = part[0];
        sRD[warp_n * 128 + r0 +  8] = part[1];
        sRD[warp_n * 128 + r0 + 16] = part[2];
        sRD[warp_n * 128 + r0 + 24] = part[3];
    }
    __syncthreads();

    if (tid < 128) {
        const int m = tid;
        const int k = kbase + m;
        const float s = sRD[m] + sRD[128 + m] + b3[0];
        if (k < WIN) {
            const int j = i - WIN + k;
            out[i * OUTW + k] = (j >= 0) ? (sm[i] + sm[j] + s) : 0.f;
        } else if (k == WIN) {
            out[i * OUTW + WIN] = 0.f;
        }
    }
}

// ---------------------------------------------------------------------------
extern "C" void kernel_launch(void* const* d_in, const int* in_sizes, int n_in,
                              void* d_out, int out_size) {
    const float* g  = (const float*)d_in[0];
    const float* sm = (const float*)d_in[1];
    const float* W1 = (const float*)d_in[2];
    const float* b1 = (const float*)d_in[3];
    const float* W2 = (const float*)d_in[4];
    const float* b2 = (const float*)d_in[5];
    const float* W3 = (const float*)d_in[6];
    const float* b3 = (const float*)d_in[7];
    float* out = (float*)d_out;

    cudaFuncSetAttribute(pair_mma_kernel, cudaFuncAttributeMaxDynamicSharedMemorySize,
                         SMEM_BYTES);

    proj_kernel<<<N_SPANS, 160>>>(g, W1, b1);
    prepB1t_kernel<<<HP, 512>>>(W1);
    prepB2t_kernel<<<HP, 160>>>(W2);
    pair_mma_kernel<<<2 * N_SPANS, NT, SMEM_BYTES>>>(g, sm, W3, b2, b3, out);
}

// round 6
// speedup vs baseline: 3.7524x; 1.0887x over previous
#include <cuda_runtime.h>
#include <cuda_fp16.h>
#include <cstdint>

#define N_SPANS 1024
#define D 512
#define H 150
#define HP 160
#define WIN 250
#define OUTW (WIN + 1)
#define NT 256

// byte strides
#define RA 144     // A/B stage row stride: 72 halves (64 data + 8 pad)
#define RH 336     // h1 row stride: 168 halves (160 data + 8 pad)

// SMEM byte offsets
#define OF_H1  0         // 128*336 = 43008
#define OF_A0  43008     // 128*144 = 18432
#define OF_A1  61440
#define OF_B0  79872     // 160*144 = 23040
#define OF_B1  102912
#define OF_GI  125952    // 512 f32
#define OF_B2F 128000    // 160 f32
#define OF_W3F 128640    // 160 f32
#define OF_RED 129280    // 256 f32
#define SMEM_BYTES 130304

// ---------------- device scratch -------------------------------------------
__device__ __align__(16) float  d_Agi[N_SPANS * HP];
__device__ __align__(16) float  d_Agj[N_SPANS * HP];
__device__ __align__(16) __half d_B1h[HP * D];    // W1c^T [n][k] half
__device__ __align__(16) __half d_B2h[HP * HP];   // W2^T  [n][k] half

// ---------------- helpers ---------------------------------------------------
__device__ __forceinline__ uint32_t smem_u32(const void* p) {
    uint32_t a;
    asm("{ .reg .u64 t; cvta.to.shared.u64 t, %1; cvt.u32.u64 %0, t; }" : "=r"(a) : "l"(p));
    return a;
}
__device__ __forceinline__ void mma_f16(float* c, const uint32_t* a, const uint32_t* b) {
    asm volatile(
        "mma.sync.aligned.m16n8k16.row.col.f32.f16.f16.f32 "
        "{%0,%1,%2,%3}, {%4,%5,%6,%7}, {%8,%9}, {%0,%1,%2,%3};"
        : "+f"(c[0]), "+f"(c[1]), "+f"(c[2]), "+f"(c[3])
        : "r"(a[0]), "r"(a[1]), "r"(a[2]), "r"(a[3]), "r"(b[0]), "r"(b[1]));
}
__device__ __forceinline__ void ldm_x4(uint32_t* r, uint32_t saddr) {
    asm volatile("ldmatrix.sync.aligned.m8n8.x4.shared.b16 {%0,%1,%2,%3}, [%4];"
                 : "=r"(r[0]), "=r"(r[1]), "=r"(r[2]), "=r"(r[3]) : "r"(saddr));
}
#define CP16(dst, src)  asm volatile("cp.async.cg.shared.global [%0], [%1], 16;" :: "r"(dst), "l"(src))
#define CP_COMMIT()     asm volatile("cp.async.commit_group;" ::: "memory")
#define CP_WAIT0()      asm volatile("cp.async.wait_group 0;" ::: "memory")

__device__ __forceinline__ uint32_t pack2(float a, float b) {
    __half2 h = __floats2half2_rn(a, b);
    return *(uint32_t*)&h;
}

// ---------------------------------------------------------------------------
// Prep kernels
// ---------------------------------------------------------------------------
__global__ void __launch_bounds__(160) proj_kernel(const float* __restrict__ g,
                                                   const float* __restrict__ W1,
                                                   const float* __restrict__ b1) {
    __shared__ float gs[D];
    const int i = blockIdx.x, tid = threadIdx.x;
    const float4* grow = (const float4*)(g + i * D);
    for (int q = tid; q < D / 4; q += 160) ((float4*)gs)[q] = grow[q];
    __syncthreads();
    const int h = (tid < H) ? tid : (H - 1);
    float a1 = b1[h], a2 = 0.f;
    const float* Wa = W1 + h;
    const float* Wb = W1 + D * H + h;
#pragma unroll 4
    for (int d = 0; d < D; d++) {
        const float gv = gs[d];
        a1 = fmaf(gv, Wa[d * H], a1);
        a2 = fmaf(gv, Wb[d * H], a2);
    }
    if (tid < HP) {
        d_Agi[i * HP + tid] = (tid < H) ? a1 : 0.f;
        d_Agj[i * HP + tid] = (tid < H) ? a2 : 0.f;
    }
}
__global__ void __launch_bounds__(512) prepB1h_kernel(const float* __restrict__ W1) {
    const int n = blockIdx.x;
    for (int k = threadIdx.x; k < D; k += 512) {
        const float v = (n < H) ? W1[(2 * D + k) * H + n] : 0.f;
        d_B1h[n * D + k] = __float2half_rn(v);
    }
}
__global__ void __launch_bounds__(160) prepB2h_kernel(const float* __restrict__ W2) {
    const int n = blockIdx.x, k = threadIdx.x;
    const float v = (n < H && k < H) ? W2[k * H + n] : 0.f;
    d_B2h[n * HP + k] = __float2half_rn(v);
}

// ---------------------------------------------------------------------------
// Main fused kernel: CTA = (span i, window half). M=128, N=160, fp16 k16.
// ---------------------------------------------------------------------------
__global__ void __launch_bounds__(NT, 1) pair_mma_kernel(const float* __restrict__ g,
                                                         const float* __restrict__ sm,
                                                         const float* __restrict__ W3,
                                                         const float* __restrict__ b2,
                                                         const float* __restrict__ b3,
                                                         float* __restrict__ out) {
    extern __shared__ char smc[];
    const uint32_t smb = smem_u32(smc);
    float* sGI = (float*)(smc + OF_GI);
    float* sB2 = (float*)(smc + OF_B2F);
    float* sW3 = (float*)(smc + OF_W3F);
    float* sRD = (float*)(smc + OF_RED);

    const int tid = threadIdx.x;
    const int lane = tid & 31;
    const int w = tid >> 5;
    const int gq = lane >> 2;
    const int tg = lane & 3;
    const int warp_m = w & 3;
    const int warp_n = w >> 2;

    const int i = blockIdx.x >> 1;
    const int half = blockIdx.x & 1;
    const int kbase = half * 128;

    // all-invalid CTA fast path (half 0, largest j = i-WIN+127 < 0)
    if (half == 0 && i <= WIN - 128) {
        if (tid < 128) out[i * OUTW + tid] = 0.f;
        return;
    }

    // ldmatrix lane geometry (same for A and B tiles)
    const int row_l = (lane & 7) + ((lane >> 3) & 1) * 8;
    const int col_l = (lane >> 4) * 16;          // byte offset (8 halves)
    const int OFA[2] = {OF_A0, OF_A1};
    const int OFB[2] = {OF_B0, OF_B1};

    // ---- prologue: gi, b2, w3 (f32), pre = Agi+Agj -> sH1 (half) ----------
    {
        const float4* gi4 = (const float4*)(g + i * D);
        for (int q = tid; q < D / 4; q += NT) ((float4*)sGI)[q] = gi4[q];
        for (int x = tid; x < HP; x += NT) {
            sB2[x] = (x < H) ? b2[x] : 0.f;
            sW3[x] = (x < H) ? W3[x] : 0.f;
        }
    }
#pragma unroll
    for (int it = 0; it < 10; it++) {            // 128 rows x 20 groups of 8
        const int x = tid + it * NT;
        const int m = x / 20, grp = x % 20;
        const int jc = min(max(i - WIN + kbase + m, 0), N_SPANS - 1);
        const float4 ai0 = ((const float4*)(d_Agi + i * HP + grp * 8))[0];
        const float4 ai1 = ((const float4*)(d_Agi + i * HP + grp * 8))[1];
        const float4 aj0 = ((const float4*)(d_Agj + jc * HP + grp * 8))[0];
        const float4 aj1 = ((const float4*)(d_Agj + jc * HP + grp * 8))[1];
        uint4 o;
        o.x = pack2(ai0.x + aj0.x, ai0.y + aj0.y);
        o.y = pack2(ai0.z + aj0.z, ai0.w + aj0.w);
        o.z = pack2(ai1.x + aj1.x, ai1.y + aj1.y);
        o.w = pack2(ai1.z + aj1.z, ai1.w + aj1.w);
        *(uint4*)(smc + OF_H1 + m * RH + grp * 16) = o;
    }

    float acc[2][10][4];
#pragma unroll
    for (int ma = 0; ma < 2; ma++)
#pragma unroll
        for (int na = 0; na < 10; na++)
#pragma unroll
            for (int q = 0; q < 4; q++) acc[ma][na][q] = 0.f;

    float4 pgj[4][2];   // A prefetch: 8 floats per item, 4 items

    auto cpB1 = [&](int ch, int buf) {           // 160 rows x 8 segs of 16B
#pragma unroll
        for (int it = 0; it < 5; it++) {
            const int x = tid + it * NT;
            const int n = x >> 3, seg = x & 7;
            CP16(smb + OFB[buf] + n * RA + seg * 16,
                 (const char*)(d_B1h + n * D + ch * 64) + seg * 16);
        }
    };
    auto ldA = [&](int ch) {
#pragma unroll
        for (int it = 0; it < 4; it++) {
            const int x = tid + it * NT;
            const int m = x >> 3, q = x & 7;     // 8 items of 8 floats per row
            const int jc = min(max(i - WIN + kbase + m, 0), N_SPANS - 1);
            const float4* p = (const float4*)(g + jc * D + ch * 64 + q * 8);
            pgj[it][0] = p[0];
            pgj[it][1] = p[1];
        }
    };
    auto stA = [&](int ch, int buf) {
#pragma unroll
        for (int it = 0; it < 4; it++) {
            const int x = tid + it * NT;
            const int m = x >> 3, q = x & 7;
            const float4 a0 = ((const float4*)(sGI + ch * 64 + q * 8))[0];
            const float4 a1 = ((const float4*)(sGI + ch * 64 + q * 8))[1];
            uint4 o;
            o.x = pack2(a0.x * pgj[it][0].x, a0.y * pgj[it][0].y);
            o.y = pack2(a0.z * pgj[it][0].z, a0.w * pgj[it][0].w);
            o.z = pack2(a1.x * pgj[it][1].x, a1.y * pgj[it][1].y);
            o.w = pack2(a1.z * pgj[it][1].z, a1.w * pgj[it][1].w);
            *(uint4*)(smc + OFA[buf] + m * RA + q * 16) = o;
        }
    };
    auto mma_chunk = [&](int buf) {              // 4 k16 steps
#pragma unroll
        for (int ks = 0; ks < 4; ks++) {
            uint32_t a[2][4];
#pragma unroll
            for (int ma = 0; ma < 2; ma++)
                ldm_x4(a[ma], smb + OFA[buf] + (warp_m * 32 + ma * 16 + row_l) * RA + ks * 32 + col_l);
            uint32_t b[5][4];
#pragma unroll
            for (int pr = 0; pr < 5; pr++)
                ldm_x4(b[pr], smb + OFB[buf] + (warp_n * 80 + pr * 16 + row_l) * RA + ks * 32 + col_l);
#pragma unroll
            for (int ma = 0; ma < 2; ma++)
#pragma unroll
                for (int pr = 0; pr < 5; pr++) {
                    uint32_t b0[2] = {b[pr][0], b[pr][2]};
                    uint32_t b1[2] = {b[pr][1], b[pr][3]};
                    mma_f16(acc[ma][pr * 2 + 0], a[ma], b0);
                    mma_f16(acc[ma][pr * 2 + 1], a[ma], b1);
                }
        }
    };

    // =================== GEMM1: 8 pipelined chunks of k64 ===================
    cpB1(0, 0); CP_COMMIT();
    ldA(0); stA(0, 0);
    CP_WAIT0();
    __syncthreads();
#pragma unroll 1
    for (int ch = 0; ch < 8; ch++) {
        const int cur = ch & 1, nxt = cur ^ 1;
        if (ch < 7) { cpB1(ch + 1, nxt); CP_COMMIT(); ldA(ch + 1); }
        mma_chunk(cur);
        if (ch < 7) { stA(ch + 1, nxt); CP_WAIT0(); }
        __syncthreads();
    }

    // ====== Epilogue 1: h1 = half(relu(acc + pre)) in place in sH1 ==========
    // overlap: kick off GEMM2 B chunk 0 copy first
    {
#pragma unroll
        for (int it = 0; it < 5; it++) {
            const int x = tid + it * NT;
            const int n = x >> 3, seg = x & 7;
            CP16(smb + OF_B0 + n * RA + seg * 16,
                 (const char*)(d_B2h + n * HP) + seg * 16);
        }
        CP_COMMIT();
    }
#pragma unroll
    for (int ma = 0; ma < 2; ma++) {
        const int r0 = warp_m * 32 + ma * 16 + gq;
#pragma unroll
        for (int na = 0; na < 10; na++) {
            const int c0 = warp_n * 80 + na * 8 + tg * 2;
            uint32_t* p0 = (uint32_t*)(smc + OF_H1 + r0 * RH + c0 * 2);
            uint32_t* p1 = (uint32_t*)(smc + OF_H1 + (r0 + 8) * RH + c0 * 2);
            const float2 pre0 = __half22float2(*(__half2*)p0);
            const float2 pre1 = __half22float2(*(__half2*)p1);
            *p0 = pack2(fmaxf(acc[ma][na][0] + pre0.x, 0.f),
                        fmaxf(acc[ma][na][1] + pre0.y, 0.f));
            *p1 = pack2(fmaxf(acc[ma][na][2] + pre1.x, 0.f),
                        fmaxf(acc[ma][na][3] + pre1.y, 0.f));
        }
    }
#pragma unroll
    for (int ma = 0; ma < 2; ma++)
#pragma unroll
        for (int na = 0; na < 10; na++)
#pragma unroll
            for (int q = 0; q < 4; q++) acc[ma][na][q] = 0.f;
    CP_WAIT0();
    __syncthreads();

    // =================== GEMM2: 3 chunks (k64, k64, k32), A = sH1 ===========
#pragma unroll 1
    for (int ch = 0; ch < 3; ch++) {
        const int cur = ch & 1, nxt = cur ^ 1;
        if (ch < 2) {
            const int nseg = (ch == 1) ? 4 : 8;        // next chunk seg count
            const int items = HP * nseg;
#pragma unroll
            for (int it = 0; it < 5; it++) {
                const int x = tid + it * NT;
                if (x < items) {
                    const int n = x / nseg, seg = x % nseg;
                    CP16(smb + OFB[nxt] + n * RA + seg * 16,
                         (const char*)(d_B2h + n * HP + (ch + 1) * 64) + seg * 16);
                }
            }
            CP_COMMIT();
        }
        const int nks = (ch < 2) ? 4 : 2;
        const int kc0 = ch * 64;
        for (int ks = 0; ks < nks; ks++) {
            uint32_t a[2][4];
#pragma unroll
            for (int ma = 0; ma < 2; ma++)
                ldm_x4(a[ma], smb + OF_H1 + (warp_m * 32 + ma * 16 + row_l) * RH + (kc0 + ks * 16) * 2 + col_l);
            uint32_t b[5][4];
#pragma unroll
            for (int pr = 0; pr < 5; pr++)
                ldm_x4(b[pr], smb + OFB[cur] + (warp_n * 80 + pr * 16 + row_l) * RA + ks * 32 + col_l);
#pragma unroll
            for (int ma = 0; ma < 2; ma++)
#pragma unroll
                for (int pr = 0; pr < 5; pr++) {
                    uint32_t b0[2] = {b[pr][0], b[pr][2]};
                    uint32_t b1[2] = {b[pr][1], b[pr][3]};
                    mma_f16(acc[ma][pr * 2 + 0], a[ma], b0);
                    mma_f16(acc[ma][pr * 2 + 1], a[ma], b1);
                }
        }
        if (ch < 2) CP_WAIT0();
        __syncthreads();
    }

    // ====== Epilogue 2: s[m] = sum_h relu(acc + b2[h]) * W3[h] ==============
    float part[4] = {0.f, 0.f, 0.f, 0.f};
#pragma unroll
    for (int ma = 0; ma < 2; ma++) {
#pragma unroll
        for (int na = 0; na < 10; na++) {
            const int c0 = warp_n * 80 + na * 8 + tg * 2;
            const float2 bb = *(const float2*)(sB2 + c0);
            const float2 ww = *(const float2*)(sW3 + c0);
            part[ma * 2 + 0] += fmaxf(acc[ma][na][0] + bb.x, 0.f) * ww.x
                              + fmaxf(acc[ma][na][1] + bb.y, 0.f) * ww.y;
            part[ma * 2 + 1] += fmaxf(acc[ma][na][2] + bb.x, 0.f) * ww.x
                              + fmaxf(acc[ma][na][3] + bb.y, 0.f) * ww.y;
        }
    }
#pragma unroll
    for (int q = 0; q < 4; q++) {
        part[q] += __shfl_xor_sync(0xffffffffu, part[q], 1);
        part[q] += __shfl_xor_sync(0xffffffffu, part[q], 2);
    }
    if (tg == 0) {
        const int r0 = warp_m * 32 + gq;
        sRD[warp_n * 128 + r0 +  0] = part[0];
        sRD[warp_n * 128 + r0 +  8] = part[1];
        sRD[warp_n * 128 + r0 + 16] = part[2];
        sRD[warp_n * 128 + r0 + 24] = part[3];
    }
    __syncthreads();

    if (tid < 128) {
        const int m = tid;
        const int k = kbase + m;
        const float s = sRD[m] + sRD[128 + m] + b3[0];
        if (k < WIN) {
            const int j = i - WIN + k;
            out[i * OUTW + k] = (j >= 0) ? (sm[i] + sm[j] + s) : 0.f;
        } else if (k == WIN) {
            out[i * OUTW + WIN] = 0.f;
        }
    }
}

// ---------------------------------------------------------------------------
extern "C" void kernel_launch(void* const* d_in, const int* in_sizes, int n_in,
                              void* d_out, int out_size) {
    const float* g  = (const float*)d_in[0];
    const float* sm = (const float*)d_in[1];
    const float* W1 = (const float*)d_in[2];
    const float* b1 = (const float*)d_in[3];
    const float* W2 = (const float*)d_in[4];
    const float* b2 = (const float*)d_in[5];
    const float* W3 = (const float*)d_in[6];
    const float* b3 = (const float*)d_in[7];
    float* out = (float*)d_out;

    cudaFuncSetAttribute(pair_mma_kernel, cudaFuncAttributeMaxDynamicSharedMemorySize,
                         SMEM_BYTES);

    proj_kernel<<<N_SPANS, 160>>>(g, W1, b1);
    prepB1h_kernel<<<HP, 512>>>(W1);
    prepB2h_kernel<<<HP, 160>>>(W2);
    pair_mma_kernel<<<2 * N_SPANS, NT, SMEM_BYTES>>>(g, sm, W3, b2, b3, out);
}

// round 8
// speedup vs baseline: 4.7022x; 1.2531x over previous
#include <cuda_runtime.h>
#include <cuda_fp16.h>
#include <cstdint>

#define N_SPANS 1024
#define D 512
#define H 150
#define HP 160
#define WIN 250
#define OUTW (WIN + 1)
#define NT 512

// byte strides
#define RA 272     // stage row stride: 136 halves (128 data + 8 pad)
#define RH 336     // h1 row stride: 168 halves (160 data + 8 pad)

// SMEM byte offsets
#define OF_H1  0         // 128*336  = 43008
#define OF_A0  43008     // 128*272  = 34816
#define OF_A1  77824
#define OF_B0  112640    // 160*272  = 43520
#define OF_B1  156160
#define OF_B2F 199680    // 160 f32
#define OF_W3F 200320    // 160 f32
#define OF_RED 200960    // 512 f32
#define SMEM_BYTES 203008

// ---------------- device scratch -------------------------------------------
__device__ __align__(16) float  d_Agi[N_SPANS * HP];
__device__ __align__(16) float  d_Agj[N_SPANS * HP];
__device__ __align__(16) __half d_B1h[HP * D];          // W1c^T [h][d]
__device__ __align__(16) __half d_B2h[HP * HP];         // W2^T  [h][k]
__device__ __align__(16) __half d_gh[N_SPANS * D];      // g in half
__device__ __align__(16) __half d_Bp[(size_t)N_SPANS * HP * D];  // B'_i[h][d] = gi[d]*W1c^T[h][d]

// ---------------- helpers ---------------------------------------------------
__device__ __forceinline__ uint32_t smem_u32(const void* p) {
    uint32_t a;
    asm("{ .reg .u64 t; cvta.to.shared.u64 t, %1; cvt.u32.u64 %0, t; }" : "=r"(a) : "l"(p));
    return a;
}
__device__ __forceinline__ void mma_f16(float* c, const uint32_t* a, const uint32_t* b) {
    asm volatile(
        "mma.sync.aligned.m16n8k16.row.col.f32.f16.f16.f32 "
        "{%0,%1,%2,%3}, {%4,%5,%6,%7}, {%8,%9}, {%0,%1,%2,%3};"
        : "+f"(c[0]), "+f"(c[1]), "+f"(c[2]), "+f"(c[3])
        : "r"(a[0]), "r"(a[1]), "r"(a[2]), "r"(a[3]), "r"(b[0]), "r"(b[1]));
}
__device__ __forceinline__ void ldm_x4(uint32_t* r, uint32_t saddr) {
    asm volatile("ldmatrix.sync.aligned.m8n8.x4.shared.b16 {%0,%1,%2,%3}, [%4];"
                 : "=r"(r[0]), "=r"(r[1]), "=r"(r[2]), "=r"(r[3]) : "r"(saddr));
}
__device__ __forceinline__ void ldm_x2(uint32_t* r, uint32_t saddr) {
    asm volatile("ldmatrix.sync.aligned.m8n8.x2.shared.b16 {%0,%1}, [%2];"
                 : "=r"(r[0]), "=r"(r[1]) : "r"(saddr));
}
#define CP16(dst, src)  asm volatile("cp.async.cg.shared.global [%0], [%1], 16;" :: "r"(dst), "l"(src))
#define CP_COMMIT()     asm volatile("cp.async.commit_group;" ::: "memory")
#define CP_WAIT0()      asm volatile("cp.async.wait_group 0;" ::: "memory")
#define CP_WAIT1()      asm volatile("cp.async.wait_group 1;" ::: "memory")

__device__ __forceinline__ uint32_t pack2(float a, float b) {
    __half2 h = __floats2half2_rn(a, b);
    return *(uint32_t*)&h;
}

// ---------------------------------------------------------------------------
// Prep kernels
// ---------------------------------------------------------------------------
__global__ void __launch_bounds__(160) proj_kernel(const float* __restrict__ g,
                                                   const float* __restrict__ W1,
                                                   const float* __restrict__ b1) {
    __shared__ float gs[D];
    const int i = blockIdx.x, tid = threadIdx.x;
    const float4* grow = (const float4*)(g + i * D);
    for (int q = tid; q < D / 4; q += 160) ((float4*)gs)[q] = grow[q];
    __syncthreads();
    const int h = (tid < H) ? tid : (H - 1);
    float a1 = b1[h], a2 = 0.f;
    const float* Wa = W1 + h;
    const float* Wb = W1 + D * H + h;
#pragma unroll 4
    for (int d = 0; d < D; d++) {
        const float gv = gs[d];
        a1 = fmaf(gv, Wa[d * H], a1);
        a2 = fmaf(gv, Wb[d * H], a2);
    }
    if (tid < HP) {
        d_Agi[i * HP + tid] = (tid < H) ? a1 : 0.f;
        d_Agj[i * HP + tid] = (tid < H) ? a2 : 0.f;
    }
}
__global__ void __launch_bounds__(512) prepB1h_kernel(const float* __restrict__ W1) {
    const int n = blockIdx.x;
    for (int k = threadIdx.x; k < D; k += 512) {
        const float v = (n < H) ? W1[(2 * D + k) * H + n] : 0.f;
        d_B1h[n * D + k] = __float2half_rn(v);
    }
}
__global__ void __launch_bounds__(160) prepB2h_kernel(const float* __restrict__ W2) {
    const int n = blockIdx.x, k = threadIdx.x;
    const float v = (n < H && k < H) ? W2[k * H + n] : 0.f;
    d_B2h[n * HP + k] = __float2half_rn(v);
}
__global__ void __launch_bounds__(256) prepGh_kernel(const float* __restrict__ g) {
    const int i = blockIdx.x, tid = threadIdx.x;
#pragma unroll
    for (int q = 0; q < 2; q++) {
        const int d = tid + q * 256;
        d_gh[i * D + d] = __float2half_rn(g[i * D + d]);
    }
}
// B'_i[h][d] = gi[d] * W1c^T[h][d]
__global__ void __launch_bounds__(512) prepBp_kernel(const float* __restrict__ g) {
    __shared__ float gs[D];
    const int i = blockIdx.x, tid = threadIdx.x;
    for (int q = tid; q < D / 4; q += 512) ((float4*)gs)[q] = ((const float4*)(g + i * D))[q];
    __syncthreads();
    __half* dst = d_Bp + (size_t)i * (HP * D);
#pragma unroll 1
    for (int it = 0; it < 20; it++) {
        const int idx = it * (512 * 8) + tid * 8;      // 8 halves per item
        const int h = idx >> 9, d = idx & 511;
        uint4 w = *(const uint4*)(d_B1h + h * D + d);
        const __half2* wp = (const __half2*)&w;
        uint4 o;
        uint32_t* op = (uint32_t*)&o;
#pragma unroll
        for (int q = 0; q < 4; q++) {
            const float2 wv = __half22float2(wp[q]);
            op[q] = pack2(wv.x * gs[d + q * 2], wv.y * gs[d + q * 2 + 1]);
        }
        *(uint4*)(dst + h * D + d) = o;
    }
}

// ---------------------------------------------------------------------------
// Main fused kernel: CTA = (span i, window half). M=128, N=160, 16 warps 4x4.
// ---------------------------------------------------------------------------
__global__ void __launch_bounds__(NT, 1) pair_mma_kernel(const float* __restrict__ sm,
                                                         const float* __restrict__ W3,
                                                         const float* __restrict__ b2,
                                                         const float* __restrict__ b3,
                                                         float* __restrict__ out) {
    extern __shared__ char smc[];
    const uint32_t smb = smem_u32(smc);
    float* sB2 = (float*)(smc + OF_B2F);
    float* sW3 = (float*)(smc + OF_W3F);
    float* sRD = (float*)(smc + OF_RED);

    const int tid = threadIdx.x;
    const int lane = tid & 31;
    const int w = tid >> 5;
    const int gq = lane >> 2;
    const int tg = lane & 3;
    const int warp_m = w & 3;       // 4 m-groups of 32 rows
    const int warp_n = w >> 2;      // 4 n-groups of 40 cols

    const int i = blockIdx.x >> 1;
    const int half = blockIdx.x & 1;
    const int kbase = half * 128;

    if (half == 0 && i <= WIN - 128) {     // fully invalid
        if (tid < 128) out[i * OUTW + tid] = 0.f;
        return;
    }

    // ldmatrix lane geometry
    const int row_l = (lane & 7) + ((lane >> 3) & 1) * 8;
    const int col_l = (lane >> 4) * 16;            // bytes
    const int rowB2l = lane & 7;                   // x2 variant
    const int colB2l = ((lane >> 3) & 1) * 16;
    const int OFA[2] = {OF_A0, OF_A1};
    const int OFB[2] = {OF_B0, OF_B1};

    // ---- prologue: b2/w3 stage + h1pre = Agi + Agj (half, into sH1)
    for (int x = tid; x < HP; x += NT) {
        sB2[x] = (x < H) ? b2[x] : 0.f;
        sW3[x] = (x < H) ? W3[x] : 0.f;
    }
#pragma unroll
    for (int it = 0; it < 5; it++) {               // 128 rows x 20 groups of 8
        const int x = tid + it * NT;
        const int m = x / 20, grp = x % 20;
        const int jc = min(max(i - WIN + kbase + m, 0), N_SPANS - 1);
        const float4 ai0 = ((const float4*)(d_Agi + i * HP + grp * 8))[0];
        const float4 ai1 = ((const float4*)(d_Agi + i * HP + grp * 8))[1];
        const float4 aj0 = ((const float4*)(d_Agj + jc * HP + grp * 8))[0];
        const float4 aj1 = ((const float4*)(d_Agj + jc * HP + grp * 8))[1];
        uint4 o;
        o.x = pack2(ai0.x + aj0.x, ai0.y + aj0.y);
        o.y = pack2(ai0.z + aj0.z, ai0.w + aj0.w);
        o.z = pack2(ai1.x + aj1.x, ai1.y + aj1.y);
        o.w = pack2(ai1.z + aj1.z, ai1.w + aj1.w);
        *(uint4*)(smc + OF_H1 + m * RH + grp * 16) = o;
    }

    float acc[2][5][4];
#pragma unroll
    for (int ma = 0; ma < 2; ma++)
#pragma unroll
        for (int na = 0; na < 5; na++)
#pragma unroll
            for (int q = 0; q < 4; q++) acc[ma][na][q] = 0.f;

    const __half* Bp = d_Bp + (size_t)i * (HP * D);

    // copy one k128 chunk of A (gj rows) + B' via cp.async
    auto cp_chunk1 = [&](int ch, int buf) {
#pragma unroll
        for (int it = 0; it < 4; it++) {           // A: 128 rows x 16 segs
            const int x = tid + it * NT;
            const int m = x >> 4, seg = x & 15;
            const int jc = min(max(i - WIN + kbase + m, 0), N_SPANS - 1);
            CP16(smb + OFA[buf] + m * RA + seg * 16,
                 (const char*)(d_gh + jc * D + ch * 128) + seg * 16);
        }
#pragma unroll
        for (int it = 0; it < 5; it++) {           // B: 160 rows x 16 segs
            const int x = tid + it * NT;
            const int n = x >> 4, seg = x & 15;
            CP16(smb + OFB[buf] + n * RA + seg * 16,
                 (const char*)(Bp + n * D + ch * 128) + seg * 16);
        }
        CP_COMMIT();
    };

    auto mma_steps = [&](int abase, int bbase, int nks, int astride) {
#pragma unroll 1
        for (int ks = 0; ks < nks; ks++) {
            uint32_t a[2][4];
#pragma unroll
            for (int ma = 0; ma < 2; ma++)
                ldm_x4(a[ma], smb + abase + (warp_m * 32 + ma * 16 + row_l) * astride + ks * 32 + col_l);
            uint32_t b[5][2];
            {
                uint32_t t[4];
#pragma unroll
                for (int pr = 0; pr < 2; pr++) {
                    ldm_x4(t, smb + bbase + (warp_n * 40 + pr * 16 + row_l) * RA + ks * 32 + col_l);
                    b[pr * 2 + 0][0] = t[0]; b[pr * 2 + 0][1] = t[2];
                    b[pr * 2 + 1][0] = t[1]; b[pr * 2 + 1][1] = t[3];
                }
                ldm_x2(b[4], smb + bbase + (warp_n * 40 + 32 + rowB2l) * RA + ks * 32 + colB2l);
            }
#pragma unroll
            for (int ma = 0; ma < 2; ma++)
#pragma unroll
                for (int na = 0; na < 5; na++) mma_f16(acc[ma][na], a[ma], b[na]);
        }
    };

    // =================== GEMM1: 4 pipelined k128 chunks =====================
    cp_chunk1(0, 0);
#pragma unroll 1
    for (int ch = 0; ch < 4; ch++) {
        const int cur = ch & 1;
        if (ch < 3) { cp_chunk1(ch + 1, cur ^ 1); CP_WAIT1(); } else { CP_WAIT0(); }
        __syncthreads();
        mma_steps(OFA[cur], OFB[cur], 8, RA);
        __syncthreads();
    }

    // kick off GEMM2 B chunk 0 (k128 of W2^T) into buf0
    {
#pragma unroll
        for (int it = 0; it < 5; it++) {
            const int x = tid + it * NT;
            const int n = x >> 4, seg = x & 15;
            CP16(smb + OF_B0 + n * RA + seg * 16,
                 (const char*)(d_B2h + n * HP) + seg * 16);
        }
        CP_COMMIT();
    }

    // ====== Epilogue 1: h1 = half(relu(acc + pre)) in place in sH1 ==========
#pragma unroll
    for (int ma = 0; ma < 2; ma++) {
        const int r0 = warp_m * 32 + ma * 16 + gq;
#pragma unroll
        for (int na = 0; na < 5; na++) {
            const int c0 = warp_n * 40 + na * 8 + tg * 2;
            uint32_t* p0 = (uint32_t*)(smc + OF_H1 + r0 * RH + c0 * 2);
            uint32_t* p1 = (uint32_t*)(smc + OF_H1 + (r0 + 8) * RH + c0 * 2);
            const float2 pre0 = __half22float2(*(__half2*)p0);
            const float2 pre1 = __half22float2(*(__half2*)p1);
            *p0 = pack2(fmaxf(acc[ma][na][0] + pre0.x, 0.f),
                        fmaxf(acc[ma][na][1] + pre0.y, 0.f));
            *p1 = pack2(fmaxf(acc[ma][na][2] + pre1.x, 0.f),
                        fmaxf(acc[ma][na][3] + pre1.y, 0.f));
        }
    }
#pragma unroll
    for (int ma = 0; ma < 2; ma++)
#pragma unroll
        for (int na = 0; na < 5; na++)
#pragma unroll
            for (int q = 0; q < 4; q++) acc[ma][na][q] = 0.f;
    CP_WAIT0();
    __syncthreads();

    // =================== GEMM2: A = sH1 (K=160), B double-buffered ==========
    {
        // copy chunk 1 (k32) into buf1 while chunk-0 MMAs run
#pragma unroll
        for (int it = 0; it < 2; it++) {
            const int x = tid + it * NT;
            if (x < HP * 4) {
                const int n = x >> 2, seg = x & 3;
                CP16(smb + OF_B1 + n * RA + seg * 16,
                     (const char*)(d_B2h + n * HP + 128) + seg * 16);
            }
        }
        CP_COMMIT();
    }
    mma_steps(OF_H1, OF_B0, 8, RH);
    CP_WAIT0();
    __syncthreads();
    // last 2 k16 steps (k 128..159) from buf1; A cols 128.. in sH1
    {
#pragma unroll 1
        for (int ks = 0; ks < 2; ks++) {
            uint32_t a[2][4];
#pragma unroll
            for (int ma = 0; ma < 2; ma++)
                ldm_x4(a[ma], smb + OF_H1 + (warp_m * 32 + ma * 16 + row_l) * RH + 256 + ks * 32 + col_l);
            uint32_t b[5][2];
            {
                uint32_t t[4];
#pragma unroll
                for (int pr = 0; pr < 2; pr++) {
                    ldm_x4(t, smb + OF_B1 + (warp_n * 40 + pr * 16 + row_l) * RA + ks * 32 + col_l);
                    b[pr * 2 + 0][0] = t[0]; b[pr * 2 + 0][1] = t[2];
                    b[pr * 2 + 1][0] = t[1]; b[pr * 2 + 1][1] = t[3];
                }
                ldm_x2(b[4], smb + OF_B1 + (warp_n * 40 + 32 + rowB2l) * RA + ks * 32 + colB2l);
            }
#pragma unroll
            for (int ma = 0; ma < 2; ma++)
#pragma unroll
                for (int na = 0; na < 5; na++) mma_f16(acc[ma][na], a[ma], b[na]);
        }
    }

    // ====== Epilogue 2: s[m] = sum_h relu(acc + b2[h]) * W3[h] ==============
    float part[4] = {0.f, 0.f, 0.f, 0.f};
#pragma unroll
    for (int ma = 0; ma < 2; ma++) {
#pragma unroll
        for (int na = 0; na < 5; na++) {
            const int c0 = warp_n * 40 + na * 8 + tg * 2;
            const float2 bb = *(const float2*)(sB2 + c0);
            const float2 ww = *(const float2*)(sW3 + c0);
            part[ma * 2 + 0] += fmaxf(acc[ma][na][0] + bb.x, 0.f) * ww.x
                              + fmaxf(acc[ma][na][1] + bb.y, 0.f) * ww.y;
            part[ma * 2 + 1] += fmaxf(acc[ma][na][2] + bb.x, 0.f) * ww.x
                              + fmaxf(acc[ma][na][3] + bb.y, 0.f) * ww.y;
        }
    }
#pragma unroll
    for (int q = 0; q < 4; q++) {
        part[q] += __shfl_xor_sync(0xffffffffu, part[q], 1);
        part[q] += __shfl_xor_sync(0xffffffffu, part[q], 2);
    }
    __syncthreads();   // sRD overlaps nothing, but ensure acc reads done before reuse
    if (tg == 0) {
        const int r0 = warp_m * 32 + gq;
        sRD[warp_n * 128 + r0 +  0] = part[0];
        sRD[warp_n * 128 + r0 +  8] = part[1];
        sRD[warp_n * 128 + r0 + 16] = part[2];
        sRD[warp_n * 128 + r0 + 24] = part[3];
    }
    __syncthreads();

    if (tid < 128) {
        const int m = tid;
        const int k = kbase + m;
        const float s = sRD[m] + sRD[128 + m] + sRD[256 + m] + sRD[384 + m] + b3[0];
        if (k < WIN) {
            const int j = i - WIN + k;
            out[i * OUTW + k] = (j >= 0) ? (sm[i] + sm[j] + s) : 0.f;
        } else if (k == WIN) {
            out[i * OUTW + WIN] = 0.f;
        }
    }
}

// ---------------------------------------------------------------------------
extern "C" void kernel_launch(void* const* d_in, const int* in_sizes, int n_in,
                              void* d_out, int out_size) {
    const float* g  = (const float*)d_in[0];
    const float* sm = (const float*)d_in[1];
    const float* W1 = (const float*)d_in[2];
    const float* b1 = (const float*)d_in[3];
    const float* W2 = (const float*)d_in[4];
    const float* b2 = (const float*)d_in[5];
    const float* W3 = (const float*)d_in[6];
    const float* b3 = (const float*)d_in[7];
    float* out = (float*)d_out;

    cudaFuncSetAttribute(pair_mma_kernel, cudaFuncAttributeMaxDynamicSharedMemorySize,
                         SMEM_BYTES);

    proj_kernel<<<N_SPANS, 160>>>(g, W1, b1);
    prepB1h_kernel<<<HP, 512>>>(W1);
    prepB2h_kernel<<<HP, 160>>>(W2);
    prepGh_kernel<<<N_SPANS, 256>>>(g);
    prepBp_kernel<<<N_SPANS, 512>>>(g);
    pair_mma_kernel<<<2 * N_SPANS, NT, SMEM_BYTES>>>(sm, W3, b2, b3, out);
}

// round 10
// speedup vs baseline: 4.9659x; 1.0561x over previous
#include <cuda_runtime.h>
#include <cuda_fp16.h>
#include <cstdint>

#define N_SPANS 1024
#define D 512
#define H 150
#define HP 160
#define WIN 250
#define OUTW (WIN + 1)
#define NT 256

// byte strides
#define RA 144     // stage row stride: 72 halves (64 data + 8 pad)
#define RH 336     // h1 row stride: 168 halves (160 data + 8 pad)

// SMEM byte offsets (per-CTA total 88,320 B -> 2 CTAs/SM)
#define OF_H1  0         // 64*336  = 21504
#define OF_A0  21504     // 64*144  = 9216
#define OF_A1  30720
#define OF_B0  39936     // 160*144 = 23040
#define OF_B1  62976
#define OF_B2F 86016     // 160 f32
#define OF_W3F 86656     // 160 f32
#define OF_RED 87296     // 256 f32
#define SMEM_BYTES 88320

// ---------------- device scratch -------------------------------------------
__device__ __align__(16) float  d_Agi[N_SPANS * HP];
__device__ __align__(16) float  d_Agj[N_SPANS * HP];
__device__ __align__(16) __half d_B1h[HP * D];          // W1c^T [h][d]
__device__ __align__(16) __half d_B2h[HP * HP];         // W2^T  [h][k]
__device__ __align__(16) __half d_gh[N_SPANS * D];      // g in half
__device__ __align__(16) __half d_Bp[(size_t)N_SPANS * HP * D];  // B'_i[h][d] = gi[d]*W1c^T[h][d]

// ---------------- helpers ---------------------------------------------------
__device__ __forceinline__ uint32_t smem_u32(const void* p) {
    uint32_t a;
    asm("{ .reg .u64 t; cvta.to.shared.u64 t, %1; cvt.u32.u64 %0, t; }" : "=r"(a) : "l"(p));
    return a;
}
__device__ __forceinline__ void mma_f16(float* c, const uint32_t* a, const uint32_t* b) {
    asm volatile(
        "mma.sync.aligned.m16n8k16.row.col.f32.f16.f16.f32 "
        "{%0,%1,%2,%3}, {%4,%5,%6,%7}, {%8,%9}, {%0,%1,%2,%3};"
        : "+f"(c[0]), "+f"(c[1]), "+f"(c[2]), "+f"(c[3])
        : "r"(a[0]), "r"(a[1]), "r"(a[2]), "r"(a[3]), "r"(b[0]), "r"(b[1]));
}
__device__ __forceinline__ void ldm_x4(uint32_t* r, uint32_t saddr) {
    asm volatile("ldmatrix.sync.aligned.m8n8.x4.shared.b16 {%0,%1,%2,%3}, [%4];"
                 : "=r"(r[0]), "=r"(r[1]), "=r"(r[2]), "=r"(r[3]) : "r"(saddr));
}
__device__ __forceinline__ void ldm_x2(uint32_t* r, uint32_t saddr) {
    asm volatile("ldmatrix.sync.aligned.m8n8.x2.shared.b16 {%0,%1}, [%2];"
                 : "=r"(r[0]), "=r"(r[1]) : "r"(saddr));
}
#define CP16(dst, src)  asm volatile("cp.async.cg.shared.global [%0], [%1], 16;" :: "r"(dst), "l"(src))
#define CP_COMMIT()     asm volatile("cp.async.commit_group;" ::: "memory")
#define CP_WAIT0()      asm volatile("cp.async.wait_group 0;" ::: "memory")
#define CP_WAIT1()      asm volatile("cp.async.wait_group 1;" ::: "memory")

__device__ __forceinline__ uint32_t pack2(float a, float b) {
    __half2 h = __floats2half2_rn(a, b);
    return *(uint32_t*)&h;
}

// ---------------------------------------------------------------------------
// Prep kernels
// ---------------------------------------------------------------------------
__global__ void __launch_bounds__(160) proj_kernel(const float* __restrict__ g,
                                                   const float* __restrict__ W1,
                                                   const float* __restrict__ b1) {
    __shared__ float gs[D];
    const int i = blockIdx.x, tid = threadIdx.x;
    const float4* grow = (const float4*)(g + i * D);
    for (int q = tid; q < D / 4; q += 160) ((float4*)gs)[q] = grow[q];
    __syncthreads();
    const int h = (tid < H) ? tid : (H - 1);
    float a1 = b1[h], a2 = 0.f;
    const float* Wa = W1 + h;
    const float* Wb = W1 + D * H + h;
#pragma unroll 4
    for (int d = 0; d < D; d++) {
        const float gv = gs[d];
        a1 = fmaf(gv, Wa[d * H], a1);
        a2 = fmaf(gv, Wb[d * H], a2);
    }
    if (tid < HP) {
        d_Agi[i * HP + tid] = (tid < H) ? a1 : 0.f;
        d_Agj[i * HP + tid] = (tid < H) ? a2 : 0.f;
    }
}
__global__ void __launch_bounds__(512) prepB1h_kernel(const float* __restrict__ W1) {
    const int n = blockIdx.x;
    for (int k = threadIdx.x; k < D; k += 512) {
        const float v = (n < H) ? W1[(2 * D + k) * H + n] : 0.f;
        d_B1h[n * D + k] = __float2half_rn(v);
    }
}
__global__ void __launch_bounds__(160) prepB2h_kernel(const float* __restrict__ W2) {
    const int n = blockIdx.x, k = threadIdx.x;
    const float v = (n < H && k < H) ? W2[k * H + n] : 0.f;
    d_B2h[n * HP + k] = __float2half_rn(v);
}
__global__ void __launch_bounds__(256) prepGh_kernel(const float* __restrict__ g) {
    const int i = blockIdx.x, tid = threadIdx.x;
#pragma unroll
    for (int q = 0; q < 2; q++) {
        const int d = tid + q * 256;
        d_gh[i * D + d] = __float2half_rn(g[i * D + d]);
    }
}
// B'_i[h][d] = gi[d] * W1c^T[h][d]
__global__ void __launch_bounds__(512) prepBp_kernel(const float* __restrict__ g) {
    __shared__ float gs[D];
    const int i = blockIdx.x, tid = threadIdx.x;
    for (int q = tid; q < D / 4; q += 512) ((float4*)gs)[q] = ((const float4*)(g + i * D))[q];
    __syncthreads();
    __half* dst = d_Bp + (size_t)i * (HP * D);
#pragma unroll 1
    for (int it = 0; it < 20; it++) {
        const int idx = it * (512 * 8) + tid * 8;
        const int h = idx >> 9, d = idx & 511;
        uint4 w = *(const uint4*)(d_B1h + h * D + d);
        const __half2* wp = (const __half2*)&w;
        uint4 o;
        uint32_t* op = (uint32_t*)&o;
#pragma unroll
        for (int q = 0; q < 4; q++) {
            const float2 wv = __half22float2(wp[q]);
            op[q] = pack2(wv.x * gs[d + q * 2], wv.y * gs[d + q * 2 + 1]);
        }
        *(uint4*)(dst + h * D + d) = o;
    }
}

// ---------------------------------------------------------------------------
// Main fused kernel: CTA = (span i, window quarter). M=64, N=160, 8 warps 2x4.
// ---------------------------------------------------------------------------
__global__ void __launch_bounds__(NT, 2) pair_mma_kernel(const float* __restrict__ sm,
                                                         const float* __restrict__ W3,
                                                         const float* __restrict__ b2,
                                                         const float* __restrict__ b3,
                                                         float* __restrict__ out) {
    extern __shared__ char smc[];
    const uint32_t smb = smem_u32(smc);
    float* sB2 = (float*)(smc + OF_B2F);
    float* sW3 = (float*)(smc + OF_W3F);
    float* sRD = (float*)(smc + OF_RED);

    const int tid = threadIdx.x;
    const int lane = tid & 31;
    const int w = tid >> 5;
    const int gq = lane >> 2;
    const int tg = lane & 3;
    const int warp_m = w & 1;       // 2 m-groups of 32 rows
    const int warp_n = w >> 1;      // 4 n-groups of 40 cols

    const int i = blockIdx.x >> 2;
    const int quarter = blockIdx.x & 3;
    const int kbase = quarter * 64;

    // fully-invalid CTA fast path: max j = i - WIN + kbase + 63 < 0
    if (i - WIN + kbase + 63 < 0) {
        if (tid < 64) out[i * OUTW + kbase + tid] = 0.f;
        return;
    }

    // ldmatrix lane geometry
    const int row_l = (lane & 7) + ((lane >> 3) & 1) * 8;
    const int col_l = (lane >> 4) * 16;            // bytes
    const int rowB2l = lane & 7;                   // x2 variant
    const int colB2l = ((lane >> 3) & 1) * 16;
    const int OFA[2] = {OF_A0, OF_A1};
    const int OFB[2] = {OF_B0, OF_B1};

    // ---- prologue: b2/w3 stage + h1pre = Agi + Agj (half, into sH1)
    for (int x = tid; x < HP; x += NT) {
        sB2[x] = (x < H) ? b2[x] : 0.f;
        sW3[x] = (x < H) ? W3[x] : 0.f;
    }
#pragma unroll
    for (int it = 0; it < 5; it++) {               // 64 rows x 20 groups of 8
        const int x = tid + it * NT;
        const int m = x / 20, grp = x % 20;
        const int jc = min(max(i - WIN + kbase + m, 0), N_SPANS - 1);
        const float4 ai0 = ((const float4*)(d_Agi + i * HP + grp * 8))[0];
        const float4 ai1 = ((const float4*)(d_Agi + i * HP + grp * 8))[1];
        const float4 aj0 = ((const float4*)(d_Agj + jc * HP + grp * 8))[0];
        const float4 aj1 = ((const float4*)(d_Agj + jc * HP + grp * 8))[1];
        uint4 o;
        o.x = pack2(ai0.x + aj0.x, ai0.y + aj0.y);
        o.y = pack2(ai0.z + aj0.z, ai0.w + aj0.w);
        o.z = pack2(ai1.x + aj1.x, ai1.y + aj1.y);
        o.w = pack2(ai1.z + aj1.z, ai1.w + aj1.w);
        *(uint4*)(smc + OF_H1 + m * RH + grp * 16) = o;
    }

    float acc[2][5][4];
#pragma unroll
    for (int ma = 0; ma < 2; ma++)
#pragma unroll
        for (int na = 0; na < 5; na++)
#pragma unroll
            for (int q = 0; q < 4; q++) acc[ma][na][q] = 0.f;

    const __half* Bp = d_Bp + (size_t)i * (HP * D);

    // copy one k64 chunk (64 halves = 128 B = 8 x 16B segs per row)
    auto cp_chunk1 = [&](int ch, int buf) {
#pragma unroll
        for (int it = 0; it < 2; it++) {           // A: 64 rows x 8 segs = 512
            const int x = tid + it * NT;
            const int m = x >> 3, seg = x & 7;
            const int jc = min(max(i - WIN + kbase + m, 0), N_SPANS - 1);
            CP16(smb + OFA[buf] + m * RA + seg * 16,
                 (const char*)(d_gh + jc * D + ch * 64) + seg * 16);
        }
#pragma unroll
        for (int it = 0; it < 5; it++) {           // B: 160 rows x 8 segs = 1280
            const int x = tid + it * NT;
            const int n = x >> 3, seg = x & 7;
            CP16(smb + OFB[buf] + n * RA + seg * 16,
                 (const char*)(Bp + n * D + ch * 64) + seg * 16);
        }
        CP_COMMIT();
    };

    auto mma_steps = [&](int abase, int bbase, int aks0, int nks, int astride) {
#pragma unroll 1
        for (int ks = 0; ks < nks; ks++) {
            uint32_t a[2][4];
#pragma unroll
            for (int ma = 0; ma < 2; ma++)
                ldm_x4(a[ma], smb + abase + (warp_m * 32 + ma * 16 + row_l) * astride + (aks0 + ks) * 32 + col_l);
            uint32_t b[5][2];
            {
                uint32_t t[4];
#pragma unroll
                for (int pr = 0; pr < 2; pr++) {
                    ldm_x4(t, smb + bbase + (warp_n * 40 + pr * 16 + row_l) * RA + ks * 32 + col_l);
                    b[pr * 2 + 0][0] = t[0]; b[pr * 2 + 0][1] = t[2];
                    b[pr * 2 + 1][0] = t[1]; b[pr * 2 + 1][1] = t[3];
                }
                ldm_x2(b[4], smb + bbase + (warp_n * 40 + 32 + rowB2l) * RA + ks * 32 + colB2l);
            }
#pragma unroll
            for (int ma = 0; ma < 2; ma++)
#pragma unroll
                for (int na = 0; na < 5; na++) mma_f16(acc[ma][na], a[ma], b[na]);
        }
    };

    // =================== GEMM1: 8 pipelined k64 chunks ======================
    cp_chunk1(0, 0);
#pragma unroll 1
    for (int ch = 0; ch < 8; ch++) {
        const int cur = ch & 1;
        if (ch < 7) { cp_chunk1(ch + 1, cur ^ 1); CP_WAIT1(); } else { CP_WAIT0(); }
        __syncthreads();
        mma_steps(OFA[cur], OFB[cur], 0, 4, RA);
        __syncthreads();
    }

    // kick off GEMM2 B chunk 0 (k64 of W2^T) into buf0
    {
#pragma unroll
        for (int it = 0; it < 5; it++) {
            const int x = tid + it * NT;
            const int n = x >> 3, seg = x & 7;
            CP16(smb + OF_B0 + n * RA + seg * 16,
                 (const char*)(d_B2h + n * HP) + seg * 16);
        }
        CP_COMMIT();
    }

    // ====== Epilogue 1: h1 = half(relu(acc + pre)) in place in sH1 ==========
#pragma unroll
    for (int ma = 0; ma < 2; ma++) {
        const int r0 = warp_m * 32 + ma * 16 + gq;
#pragma unroll
        for (int na = 0; na < 5; na++) {
            const int c0 = warp_n * 40 + na * 8 + tg * 2;
            uint32_t* p0 = (uint32_t*)(smc + OF_H1 + r0 * RH + c0 * 2);
            uint32_t* p1 = (uint32_t*)(smc + OF_H1 + (r0 + 8) * RH + c0 * 2);
            const float2 pre0 = __half22float2(*(__half2*)p0);
            const float2 pre1 = __half22float2(*(__half2*)p1);
            *p0 = pack2(fmaxf(acc[ma][na][0] + pre0.x, 0.f),
                        fmaxf(acc[ma][na][1] + pre0.y, 0.f));
            *p1 = pack2(fmaxf(acc[ma][na][2] + pre1.x, 0.f),
                        fmaxf(acc[ma][na][3] + pre1.y, 0.f));
        }
    }
#pragma unroll
    for (int ma = 0; ma < 2; ma++)
#pragma unroll
        for (int na = 0; na < 5; na++)
#pragma unroll
            for (int q = 0; q < 4; q++) acc[ma][na][q] = 0.f;
    CP_WAIT0();
    __syncthreads();

    // ========= GEMM2: A = sH1 (K=160), 3 B chunks (k64,k64,k32) =============
#pragma unroll 1
    for (int ch = 0; ch < 3; ch++) {
        const int cur = ch & 1;
        if (ch < 2) {
            const int nseg = (ch == 1) ? 4 : 8;    // k32 : k64 of next chunk
            const int items = HP * nseg;
#pragma unroll
            for (int it = 0; it < 5; it++) {
                const int x = tid + it * NT;
                if (x < items) {
                    const int n = x / nseg, seg = x % nseg;
                    CP16(smb + OFB[cur ^ 1] + n * RA + seg * 16,
                         (const char*)(d_B2h + n * HP + (ch + 1) * 64) + seg * 16);
                }
            }
            CP_COMMIT();
        }
        mma_steps(OF_H1, OFB[cur], ch * 4, (ch < 2) ? 4 : 2, RH);
        if (ch < 2) CP_WAIT0();
        __syncthreads();
    }

    // ====== Epilogue 2: s[m] = sum_h relu(acc + b2[h]) * W3[h] ==============
    float part[4] = {0.f, 0.f, 0.f, 0.f};
#pragma unroll
    for (int ma = 0; ma < 2; ma++) {
#pragma unroll
        for (int na = 0; na < 5; na++) {
            const int c0 = warp_n * 40 + na * 8 + tg * 2;
            const float2 bb = *(const float2*)(sB2 + c0);
            const float2 ww = *(const float2*)(sW3 + c0);
            part[ma * 2 + 0] += fmaxf(acc[ma][na][0] + bb.x, 0.f) * ww.x
                              + fmaxf(acc[ma][na][1] + bb.y, 0.f) * ww.y;
            part[ma * 2 + 1] += fmaxf(acc[ma][na][2] + bb.x, 0.f) * ww.x
                              + fmaxf(acc[ma][na][3] + bb.y, 0.f) * ww.y;
        }
    }
#pragma unroll
    for (int q = 0; q < 4; q++) {
        part[q] += __shfl_xor_sync(0xffffffffu, part[q], 1);
        part[q] += __shfl_xor_sync(0xffffffffu, part[q], 2);
    }
    if (tg == 0) {
        const int r0 = warp_m * 32 + gq;
        sRD[warp_n * 64 + r0 +  0] = part[0];
        sRD[warp_n * 64 + r0 +  8] = part[1];
        sRD[warp_n * 64 + r0 + 16] = part[2];
        sRD[warp_n * 64 + r0 + 24] = part[3];
    }
    __syncthreads();

    if (tid < 64) {
        const int m = tid;
        const int k = kbase + m;
        const float s = sRD[m] + sRD[64 + m] + sRD[128 + m] + sRD[192 + m] + b3[0];
        if (k < WIN) {
            const int j = i - WIN + k;
            out[i * OUTW + k] = (j >= 0) ? (sm[i] + sm[j] + s) : 0.f;
        } else if (k == WIN) {
            out[i * OUTW + WIN] = 0.f;
        }
    }
}

// ---------------------------------------------------------------------------
extern "C" void kernel_launch(void* const* d_in, const int* in_sizes, int n_in,
                              void* d_out, int out_size) {
    const float* g  = (const float*)d_in[0];
    const float* sm = (const float*)d_in[1];
    const float* W1 = (const float*)d_in[2];
    const float* b1 = (const float*)d_in[3];
    const float* W2 = (const float*)d_in[4];
    const float* b2 = (const float*)d_in[5];
    const float* W3 = (const float*)d_in[6];
    const float* b3 = (const float*)d_in[7];
    float* out = (float*)d_out;

    cudaFuncSetAttribute(pair_mma_kernel, cudaFuncAttributeMaxDynamicSharedMemorySize,
                         SMEM_BYTES);

    proj_kernel<<<N_SPANS, 160>>>(g, W1, b1);
    prepB1h_kernel<<<HP, 512>>>(W1);
    prepB2h_kernel<<<HP, 160>>>(W2);
    prepGh_kernel<<<N_SPANS, 256>>>(g);
    prepBp_kernel<<<N_SPANS, 512>>>(g);
    pair_mma_kernel<<<4 * N_SPANS, NT, SMEM_BYTES>>>(sm, W3, b2, b3, out);
}

// round 11
// speedup vs baseline: 5.0227x; 1.0114x over previous
#include <cuda_runtime.h>
#include <cuda_fp16.h>
#include <cstdint>

#define N_SPANS 1024
#define D 512
#define H 150
#define HP 160
#define WIN 250
#define OUTW (WIN + 1)
#define NT 256

// byte strides
#define RA 144     // stage row stride: 72 halves (64 data + 8 pad)
#define RH 336     // h1 row stride: 168 halves (160 data + 8 pad)

// SMEM byte offsets (per-CTA total 88,320 B -> 2 CTAs/SM)
#define OF_H1  0         // 64*336  = 21504
#define OF_A0  21504     // 64*144  = 9216
#define OF_A1  30720
#define OF_B0  39936     // 160*144 = 23040
#define OF_B1  62976
#define OF_B2F 86016     // 160 f32
#define OF_W3F 86656     // 160 f32
#define OF_RED 87296     // 256 f32
#define SMEM_BYTES 88320

// ---------------- device scratch -------------------------------------------
__device__ __align__(16) float  d_Agi[N_SPANS * HP];
__device__ __align__(16) float  d_Agj[N_SPANS * HP];
__device__ __align__(16) __half d_B1h[HP * D];          // W1c^T [h][d]
__device__ __align__(16) __half d_B2h[HP * HP];         // W2^T  [h][k]
__device__ __align__(16) __half d_gh[N_SPANS * D];      // g in half
__device__ __align__(16) __half d_Bp[(size_t)N_SPANS * HP * D];  // B'_i[h][d] = gi[d]*W1c^T[h][d]

// ---------------- helpers ---------------------------------------------------
__device__ __forceinline__ uint32_t smem_u32(const void* p) {
    uint32_t a;
    asm("{ .reg .u64 t; cvta.to.shared.u64 t, %1; cvt.u32.u64 %0, t; }" : "=r"(a) : "l"(p));
    return a;
}
__device__ __forceinline__ void mma_f16(float* c, const uint32_t* a, const uint32_t* b) {
    asm volatile(
        "mma.sync.aligned.m16n8k16.row.col.f32.f16.f16.f32 "
        "{%0,%1,%2,%3}, {%4,%5,%6,%7}, {%8,%9}, {%0,%1,%2,%3};"
        : "+f"(c[0]), "+f"(c[1]), "+f"(c[2]), "+f"(c[3])
        : "r"(a[0]), "r"(a[1]), "r"(a[2]), "r"(a[3]), "r"(b[0]), "r"(b[1]));
}
__device__ __forceinline__ void ldm_x4(uint32_t* r, uint32_t saddr) {
    asm volatile("ldmatrix.sync.aligned.m8n8.x4.shared.b16 {%0,%1,%2,%3}, [%4];"
                 : "=r"(r[0]), "=r"(r[1]), "=r"(r[2]), "=r"(r[3]) : "r"(saddr));
}
__device__ __forceinline__ void ldm_x2(uint32_t* r, uint32_t saddr) {
    asm volatile("ldmatrix.sync.aligned.m8n8.x2.shared.b16 {%0,%1}, [%2];"
                 : "=r"(r[0]), "=r"(r[1]) : "r"(saddr));
}
#define CP16(dst, src)  asm volatile("cp.async.cg.shared.global [%0], [%1], 16;" :: "r"(dst), "l"(src))
#define CP_COMMIT()     asm volatile("cp.async.commit_group;" ::: "memory")
#define CP_WAIT0()      asm volatile("cp.async.wait_group 0;" ::: "memory")

__device__ __forceinline__ uint32_t pack2(float a, float b) {
    __half2 h = __floats2half2_rn(a, b);
    return *(uint32_t*)&h;
}

// ---------------------------------------------------------------------------
// Prep kernels
// ---------------------------------------------------------------------------
__global__ void __launch_bounds__(160) proj_kernel(const float* __restrict__ g,
                                                   const float* __restrict__ W1,
                                                   const float* __restrict__ b1) {
    __shared__ float gs[D];
    const int i = blockIdx.x, tid = threadIdx.x;
    const float4* grow = (const float4*)(g + i * D);
    for (int q = tid; q < D / 4; q += 160) ((float4*)gs)[q] = grow[q];
    __syncthreads();
    const int h = (tid < H) ? tid : (H - 1);
    float a1 = b1[h], a2 = 0.f;
    const float* Wa = W1 + h;
    const float* Wb = W1 + D * H + h;
#pragma unroll 4
    for (int d = 0; d < D; d++) {
        const float gv = gs[d];
        a1 = fmaf(gv, Wa[d * H], a1);
        a2 = fmaf(gv, Wb[d * H], a2);
    }
    if (tid < HP) {
        d_Agi[i * HP + tid] = (tid < H) ? a1 : 0.f;
        d_Agj[i * HP + tid] = (tid < H) ? a2 : 0.f;
    }
}
__global__ void __launch_bounds__(512) prepB1h_kernel(const float* __restrict__ W1) {
    const int n = blockIdx.x;
    for (int k = threadIdx.x; k < D; k += 512) {
        const float v = (n < H) ? W1[(2 * D + k) * H + n] : 0.f;
        d_B1h[n * D + k] = __float2half_rn(v);
    }
}
__global__ void __launch_bounds__(160) prepB2h_kernel(const float* __restrict__ W2) {
    const int n = blockIdx.x, k = threadIdx.x;
    const float v = (n < H && k < H) ? W2[k * H + n] : 0.f;
    d_B2h[n * HP + k] = __float2half_rn(v);
}
__global__ void __launch_bounds__(256) prepGh_kernel(const float* __restrict__ g) {
    const int i = blockIdx.x, tid = threadIdx.x;
#pragma unroll
    for (int q = 0; q < 2; q++) {
        const int d = tid + q * 256;
        d_gh[i * D + d] = __float2half_rn(g[i * D + d]);
    }
}
// B'_i[h][d] = gi[d] * W1c^T[h][d]
__global__ void __launch_bounds__(512) prepBp_kernel(const float* __restrict__ g) {
    __shared__ float gs[D];
    const int i = blockIdx.x, tid = threadIdx.x;
    for (int q = tid; q < D / 4; q += 512) ((float4*)gs)[q] = ((const float4*)(g + i * D))[q];
    __syncthreads();
    __half* dst = d_Bp + (size_t)i * (HP * D);
#pragma unroll 1
    for (int it = 0; it < 20; it++) {
        const int idx = it * (512 * 8) + tid * 8;
        const int h = idx >> 9, d = idx & 511;
        uint4 w = *(const uint4*)(d_B1h + h * D + d);
        const __half2* wp = (const __half2*)&w;
        uint4 o;
        uint32_t* op = (uint32_t*)&o;
#pragma unroll
        for (int q = 0; q < 4; q++) {
            const float2 wv = __half22float2(wp[q]);
            op[q] = pack2(wv.x * gs[d + q * 2], wv.y * gs[d + q * 2 + 1]);
        }
        *(uint4*)(dst + h * D + d) = o;
    }
}

// ---------------------------------------------------------------------------
// Main fused kernel: CTA = (span i, window quarter). M=64, N=160, 8 warps 2x4.
// Single-sync double-buffer pipeline in both GEMMs.
// ---------------------------------------------------------------------------
__global__ void __launch_bounds__(NT, 2) pair_mma_kernel(const float* __restrict__ sm,
                                                         const float* __restrict__ W3,
                                                         const float* __restrict__ b2,
                                                         const float* __restrict__ b3,
                                                         float* __restrict__ out) {
    extern __shared__ char smc[];
    const uint32_t smb = smem_u32(smc);
    float* sB2 = (float*)(smc + OF_B2F);
    float* sW3 = (float*)(smc + OF_W3F);
    float* sRD = (float*)(smc + OF_RED);

    const int tid = threadIdx.x;
    const int lane = tid & 31;
    const int w = tid >> 5;
    const int gq = lane >> 2;
    const int tg = lane & 3;
    const int warp_m = w & 1;       // 2 m-groups of 32 rows
    const int warp_n = w >> 1;      // 4 n-groups of 40 cols

    const int i = blockIdx.x >> 2;
    const int quarter = blockIdx.x & 3;
    const int kbase = quarter * 64;

    // fully-invalid CTA fast path: max j = i - WIN + kbase + 63 < 0
    if (i - WIN + kbase + 63 < 0) {
        if (tid < 64) out[i * OUTW + kbase + tid] = 0.f;
        return;
    }

    // ldmatrix lane geometry
    const int row_l = (lane & 7) + ((lane >> 3) & 1) * 8;
    const int col_l = (lane >> 4) * 16;            // bytes
    const int rowB2l = lane & 7;                   // x2 variant
    const int colB2l = ((lane >> 3) & 1) * 16;
    const int OFA[2] = {OF_A0, OF_A1};
    const int OFB[2] = {OF_B0, OF_B1};

    const __half* Bp = d_Bp + (size_t)i * (HP * D);

    // copy one k64 chunk (64 halves = 128 B = 8 x 16B segs per row)
    auto cp_chunk1 = [&](int ch, int buf) {
#pragma unroll
        for (int it = 0; it < 2; it++) {           // A: 64 rows x 8 segs = 512
            const int x = tid + it * NT;
            const int m = x >> 3, seg = x & 7;
            const int jc = min(max(i - WIN + kbase + m, 0), N_SPANS - 1);
            CP16(smb + OFA[buf] + m * RA + seg * 16,
                 (const char*)(d_gh + jc * D + ch * 64) + seg * 16);
        }
#pragma unroll
        for (int it = 0; it < 5; it++) {           // B: 160 rows x 8 segs = 1280
            const int x = tid + it * NT;
            const int n = x >> 3, seg = x & 7;
            CP16(smb + OFB[buf] + n * RA + seg * 16,
                 (const char*)(Bp + n * D + ch * 64) + seg * 16);
        }
        CP_COMMIT();
    };

    // ---- kick chunk 0 copy immediately, then do prologue work under it
    cp_chunk1(0, 0);

    for (int x = tid; x < HP; x += NT) {
        sB2[x] = (x < H) ? b2[x] : 0.f;
        sW3[x] = (x < H) ? W3[x] : 0.f;
    }
#pragma unroll
    for (int it = 0; it < 5; it++) {               // 64 rows x 20 groups of 8
        const int x = tid + it * NT;
        const int m = x / 20, grp = x % 20;
        const int jc = min(max(i - WIN + kbase + m, 0), N_SPANS - 1);
        const float4 ai0 = ((const float4*)(d_Agi + i * HP + grp * 8))[0];
        const float4 ai1 = ((const float4*)(d_Agi + i * HP + grp * 8))[1];
        const float4 aj0 = ((const float4*)(d_Agj + jc * HP + grp * 8))[0];
        const float4 aj1 = ((const float4*)(d_Agj + jc * HP + grp * 8))[1];
        uint4 o;
        o.x = pack2(ai0.x + aj0.x, ai0.y + aj0.y);
        o.y = pack2(ai0.z + aj0.z, ai0.w + aj0.w);
        o.z = pack2(ai1.x + aj1.x, ai1.y + aj1.y);
        o.w = pack2(ai1.z + aj1.z, ai1.w + aj1.w);
        *(uint4*)(smc + OF_H1 + m * RH + grp * 16) = o;
    }

    float acc[2][5][4];
#pragma unroll
    for (int ma = 0; ma < 2; ma++)
#pragma unroll
        for (int na = 0; na < 5; na++)
#pragma unroll
            for (int q = 0; q < 4; q++) acc[ma][na][q] = 0.f;

    auto mma_steps = [&](int abase, int bbase, int aks0, int nks, int astride) {
#pragma unroll 1
        for (int ks = 0; ks < nks; ks++) {
            uint32_t a[2][4];
#pragma unroll
            for (int ma = 0; ma < 2; ma++)
                ldm_x4(a[ma], smb + abase + (warp_m * 32 + ma * 16 + row_l) * astride + (aks0 + ks) * 32 + col_l);
            uint32_t b[5][2];
            {
                uint32_t t[4];
#pragma unroll
                for (int pr = 0; pr < 2; pr++) {
                    ldm_x4(t, smb + bbase + (warp_n * 40 + pr * 16 + row_l) * RA + ks * 32 + col_l);
                    b[pr * 2 + 0][0] = t[0]; b[pr * 2 + 0][1] = t[2];
                    b[pr * 2 + 1][0] = t[1]; b[pr * 2 + 1][1] = t[3];
                }
                ldm_x2(b[4], smb + bbase + (warp_n * 40 + 32 + rowB2l) * RA + ks * 32 + colB2l);
            }
#pragma unroll
            for (int ma = 0; ma < 2; ma++)
#pragma unroll
                for (int na = 0; na < 5; na++) mma_f16(acc[ma][na], a[ma], b[na]);
        }
    };

    // helper: stage a GEMM2 W2 chunk (k64 segments: nseg = 8 (k64) or 4 (k32))
    auto cp_chunk2 = [&](int ch, int buf) {
        const int nseg = (ch == 2) ? 4 : 8;
        const int items = HP * nseg;
#pragma unroll
        for (int it = 0; it < 5; it++) {
            const int x = tid + it * NT;
            if (x < items) {
                const int n = x / nseg, seg = x % nseg;
                CP16(smb + OFB[buf] + n * RA + seg * 16,
                     (const char*)(d_B2h + n * HP + ch * 64) + seg * 16);
            }
        }
        CP_COMMIT();
    };

    // =================== GEMM1: 8 chunks, ONE sync per chunk ================
#pragma unroll 1
    for (int ch = 0; ch < 8; ch++) {
        const int cur = ch & 1;
        CP_WAIT0();              // chunk ch fully arrived (this thread's view)
        __syncthreads();         // all warps: mma(ch-1) complete, data visible
        if (ch < 7) cp_chunk1(ch + 1, cur ^ 1);   // overlaps mma(ch)
        else        cp_chunk2(0, 0);              // hoisted GEMM2 B chunk 0 (B0 idle: last read at ch=6)
        mma_steps(OFA[cur], OFB[cur], 0, 4, RA);
    }

    // ====== Epilogue 1: h1 = half(relu(acc + pre)) in place (per-warp cells)
#pragma unroll
    for (int ma = 0; ma < 2; ma++) {
        const int r0 = warp_m * 32 + ma * 16 + gq;
#pragma unroll
        for (int na = 0; na < 5; na++) {
            const int c0 = warp_n * 40 + na * 8 + tg * 2;
            uint32_t* p0 = (uint32_t*)(smc + OF_H1 + r0 * RH + c0 * 2);
            uint32_t* p1 = (uint32_t*)(smc + OF_H1 + (r0 + 8) * RH + c0 * 2);
            const float2 pre0 = __half22float2(*(__half2*)p0);
            const float2 pre1 = __half22float2(*(__half2*)p1);
            *p0 = pack2(fmaxf(acc[ma][na][0] + pre0.x, 0.f),
                        fmaxf(acc[ma][na][1] + pre0.y, 0.f));
            *p1 = pack2(fmaxf(acc[ma][na][2] + pre1.x, 0.f),
                        fmaxf(acc[ma][na][3] + pre1.y, 0.f));
        }
    }
#pragma unroll
    for (int ma = 0; ma < 2; ma++)
#pragma unroll
        for (int na = 0; na < 5; na++)
#pragma unroll
            for (int q = 0; q < 4; q++) acc[ma][na][q] = 0.f;

    CP_WAIT0();                  // W2 chunk 0 arrived
    __syncthreads();             // h1 visible to all warps

    // ========= GEMM2: 3 chunks (k64,k64,k32), ONE sync per handoff ==========
#pragma unroll 1
    for (int ch = 0; ch < 3; ch++) {
        const int cur = ch & 1;
        if (ch < 2) cp_chunk2(ch + 1, cur ^ 1);   // prev mma on that buf synced below
        mma_steps(OF_H1, OFB[cur], ch * 4, (ch < 2) ? 4 : 2, RH);
        if (ch < 2) { CP_WAIT0(); __syncthreads(); }
    }

    // ====== Epilogue 2: s[m] = sum_h relu(acc + b2[h]) * W3[h] ==============
    float part[4] = {0.f, 0.f, 0.f, 0.f};
#pragma unroll
    for (int ma = 0; ma < 2; ma++) {
#pragma unroll
        for (int na = 0; na < 5; na++) {
            const int c0 = warp_n * 40 + na * 8 + tg * 2;
            const float2 bb = *(const float2*)(sB2 + c0);
            const float2 ww = *(const float2*)(sW3 + c0);
            part[ma * 2 + 0] += fmaxf(acc[ma][na][0] + bb.x, 0.f) * ww.x
                              + fmaxf(acc[ma][na][1] + bb.y, 0.f) * ww.y;
            part[ma * 2 + 1] += fmaxf(acc[ma][na][2] + bb.x, 0.f) * ww.x
                              + fmaxf(acc[ma][na][3] + bb.y, 0.f) * ww.y;
        }
    }
#pragma unroll
    for (int q = 0; q < 4; q++) {
        part[q] += __shfl_xor_sync(0xffffffffu, part[q], 1);
        part[q] += __shfl_xor_sync(0xffffffffu, part[q], 2);
    }
    if (tg == 0) {
        const int r0 = warp_m * 32 + gq;
        sRD[warp_n * 64 + r0 +  0] = part[0];
        sRD[warp_n * 64 + r0 +  8] = part[1];
        sRD[warp_n * 64 + r0 + 16] = part[2];
        sRD[warp_n * 64 + r0 + 24] = part[3];
    }
    __syncthreads();

    if (tid < 64) {
        const int m = tid;
        const int k = kbase + m;
        const float s = sRD[m] + sRD[64 + m] + sRD[128 + m] + sRD[192 + m] + b3[0];
        if (k < WIN) {
            const int j = i - WIN + k;
            out[i * OUTW + k] = (j >= 0) ? (sm[i] + sm[j] + s) : 0.f;
        } else if (k == WIN) {
            out[i * OUTW + WIN] = 0.f;
        }
    }
}

// ---------------------------------------------------------------------------
extern "C" void kernel_launch(void* const* d_in, const int* in_sizes, int n_in,
                              void* d_out, int out_size) {
    const float* g  = (const float*)d_in[0];
    const float* sm = (const float*)d_in[1];
    const float* W1 = (const float*)d_in[2];
    const float* b1 = (const float*)d_in[3];
    const float* W2 = (const float*)d_in[4];
    const float* b2 = (const float*)d_in[5];
    const float* W3 = (const float*)d_in[6];
    const float* b3 = (const float*)d_in[7];
    float* out = (float*)d_out;

    cudaFuncSetAttribute(pair_mma_kernel, cudaFuncAttributeMaxDynamicSharedMemorySize,
                         SMEM_BYTES);

    proj_kernel<<<N_SPANS, 160>>>(g, W1, b1);
    prepB1h_kernel<<<HP, 512>>>(W1);
    prepB2h_kernel<<<HP, 160>>>(W2);
    prepGh_kernel<<<N_SPANS, 256>>>(g);
    prepBp_kernel<<<N_SPANS, 512>>>(g);
    pair_mma_kernel<<<4 * N_SPANS, NT, SMEM_BYTES>>>(sm, W3, b2, b3, out);
}

// round 12
// speedup vs baseline: 6.6424x; 1.3225x over previous
#include <cuda_runtime.h>
#include <cuda_fp16.h>
#include <cstdint>

#define N_SPANS 1024
#define D 512
#define H 150
#define HP 160
#define WIN 250
#define OUTW (WIN + 1)
#define NT 256

// byte strides
#define RA 144     // stage row stride: 72 halves (64 data + 8 pad)
#define RH 336     // h1 row stride: 168 halves (160 data + 8 pad)

// SMEM byte offsets (per-CTA total 89,344 B -> 2 CTAs/SM)
#define OF_H1  0         // 64*336  = 21504
#define OF_A0  21504     // 64*144  = 9216
#define OF_A1  30720
#define OF_B0  39936     // 160*144 = 23040
#define OF_B1  62976
#define OF_B2F 86016     // 160 f32
#define OF_W3F 86656     // 160 f32
#define OF_RED 87296     // 256 f32
#define OF_GIH 88320     // 512 halves (gi row, half)
#define SMEM_BYTES 89344

// ---------------- device scratch -------------------------------------------
__device__ __align__(16) float  d_Agi[N_SPANS * HP];
__device__ __align__(16) float  d_Agj[N_SPANS * HP];
__device__ __align__(16) __half d_B1h[HP * D];          // W1c^T [h][d]  (raw, shared)
__device__ __align__(16) __half d_B2h[HP * HP];         // W2^T  [h][k]
__device__ __align__(16) __half d_gh[N_SPANS * D];      // g in half

// ---------------- helpers ---------------------------------------------------
__device__ __forceinline__ uint32_t smem_u32(const void* p) {
    uint32_t a;
    asm("{ .reg .u64 t; cvta.to.shared.u64 t, %1; cvt.u32.u64 %0, t; }" : "=r"(a) : "l"(p));
    return a;
}
__device__ __forceinline__ void mma_f16(float* c, const uint32_t* a, const uint32_t* b) {
    asm volatile(
        "mma.sync.aligned.m16n8k16.row.col.f32.f16.f16.f32 "
        "{%0,%1,%2,%3}, {%4,%5,%6,%7}, {%8,%9}, {%0,%1,%2,%3};"
        : "+f"(c[0]), "+f"(c[1]), "+f"(c[2]), "+f"(c[3])
        : "r"(a[0]), "r"(a[1]), "r"(a[2]), "r"(a[3]), "r"(b[0]), "r"(b[1]));
}
__device__ __forceinline__ void ldm_x4(uint32_t* r, uint32_t saddr) {
    asm volatile("ldmatrix.sync.aligned.m8n8.x4.shared.b16 {%0,%1,%2,%3}, [%4];"
                 : "=r"(r[0]), "=r"(r[1]), "=r"(r[2]), "=r"(r[3]) : "r"(saddr));
}
__device__ __forceinline__ void ldm_x2(uint32_t* r, uint32_t saddr) {
    asm volatile("ldmatrix.sync.aligned.m8n8.x2.shared.b16 {%0,%1}, [%2];"
                 : "=r"(r[0]), "=r"(r[1]) : "r"(saddr));
}
#define CP16(dst, src)  asm volatile("cp.async.cg.shared.global [%0], [%1], 16;" :: "r"(dst), "l"(src))
#define CP_COMMIT()     asm volatile("cp.async.commit_group;" ::: "memory")
#define CP_WAIT0()      asm volatile("cp.async.wait_group 0;" ::: "memory")

__device__ __forceinline__ uint32_t pack2(float a, float b) {
    __half2 h = __floats2half2_rn(a, b);
    return *(uint32_t*)&h;
}
__device__ __forceinline__ uint4 hmul4(uint4 x, uint4 y) {
    uint4 r;
    *(__half2*)&r.x = __hmul2(*(__half2*)&x.x, *(__half2*)&y.x);
    *(__half2*)&r.y = __hmul2(*(__half2*)&x.y, *(__half2*)&y.y);
    *(__half2*)&r.z = __hmul2(*(__half2*)&x.z, *(__half2*)&y.z);
    *(__half2*)&r.w = __hmul2(*(__half2*)&x.w, *(__half2*)&y.w);
    return r;
}

// ---------------------------------------------------------------------------
// Prep kernels
// ---------------------------------------------------------------------------
__global__ void __launch_bounds__(160) proj_kernel(const float* __restrict__ g,
                                                   const float* __restrict__ W1,
                                                   const float* __restrict__ b1) {
    __shared__ float gs[D];
    const int i = blockIdx.x, tid = threadIdx.x;
    const float4* grow = (const float4*)(g + i * D);
    for (int q = tid; q < D / 4; q += 160) ((float4*)gs)[q] = grow[q];
    __syncthreads();
    const int h = (tid < H) ? tid : (H - 1);
    float a1 = b1[h], a2 = 0.f;
    const float* Wa = W1 + h;
    const float* Wb = W1 + D * H + h;
#pragma unroll 4
    for (int d = 0; d < D; d++) {
        const float gv = gs[d];
        a1 = fmaf(gv, Wa[d * H], a1);
        a2 = fmaf(gv, Wb[d * H], a2);
    }
    if (tid < HP) {
        d_Agi[i * HP + tid] = (tid < H) ? a1 : 0.f;
        d_Agj[i * HP + tid] = (tid < H) ? a2 : 0.f;
    }
}

// fused: blocks [0,1024) convert g rows to half; blocks [1024,1184) build W1c^T/W2^T
__global__ void __launch_bounds__(512) prep_fused_kernel(const float* __restrict__ g,
                                                         const float* __restrict__ W1,
                                                         const float* __restrict__ W2) {
    const int b = blockIdx.x, tid = threadIdx.x;
    if (b < N_SPANS) {
        d_gh[b * D + tid] = __float2half_rn(g[b * D + tid]);
    } else {
        const int n = b - N_SPANS;          // 0..159
        const float v1 = (n < H) ? W1[(2 * D + tid) * H + n] : 0.f;
        d_B1h[n * D + tid] = __float2half_rn(v1);
        if (tid < HP) {
            const float v2 = (n < H && tid < H) ? W2[tid * H + n] : 0.f;
            d_B2h[n * HP + tid] = __float2half_rn(v2);
        }
    }
}

// ---------------------------------------------------------------------------
// Main fused kernel: CTA = (span i, window quarter). M=64, N=160, 8 warps 2x4.
// A' = gj .* gi computed on the fly (half2); B = raw W1c^T via cp.async (L2-hot).
// ---------------------------------------------------------------------------
__global__ void __launch_bounds__(NT, 2) pair_mma_kernel(const float* __restrict__ sm,
                                                         const float* __restrict__ W3,
                                                         const float* __restrict__ b2,
                                                         const float* __restrict__ b3,
                                                         float* __restrict__ out) {
    extern __shared__ char smc[];
    const uint32_t smb = smem_u32(smc);
    float* sB2 = (float*)(smc + OF_B2F);
    float* sW3 = (float*)(smc + OF_W3F);
    float* sRD = (float*)(smc + OF_RED);

    const int tid = threadIdx.x;
    const int lane = tid & 31;
    const int w = tid >> 5;
    const int gq = lane >> 2;
    const int tg = lane & 3;
    const int warp_m = w & 1;       // 2 m-groups of 32 rows
    const int warp_n = w >> 1;      // 4 n-groups of 40 cols

    const int i = blockIdx.x >> 2;
    const int quarter = blockIdx.x & 3;
    const int kbase = quarter * 64;

    // fully-invalid CTA fast path
    if (i - WIN + kbase + 63 < 0) {
        if (tid < 64) out[i * OUTW + kbase + tid] = 0.f;
        return;
    }

    // ldmatrix lane geometry
    const int row_l = (lane & 7) + ((lane >> 3) & 1) * 8;
    const int col_l = (lane >> 4) * 16;
    const int rowB2l = lane & 7;
    const int colB2l = ((lane >> 3) & 1) * 16;
    const int OFA[2] = {OF_A0, OF_A1};
    const int OFB[2] = {OF_B0, OF_B1};

    // A-fill addressing: 2 items/thread, item = (row m, 16B seg of 8 halves)
    const int am0 = tid >> 3, aseg0 = tid & 7;           // item 0
    const int am1 = (tid + NT) >> 3, aseg1 = tid & 7;    // item 1 (rows 32..63)
    const int ajc0 = min(max(i - WIN + kbase + am0, 0), N_SPANS - 1);
    const int ajc1 = min(max(i - WIN + kbase + am1, 0), N_SPANS - 1);

    // ---- stage gi (half) into smem; b2/w3 f32
    if (tid < 64) {
        *(uint4*)(smc + OF_GIH + tid * 16) = *(const uint4*)(d_gh + i * D + tid * 8);
    }
    for (int x = tid; x < HP; x += NT) {
        sB2[x] = (x < H) ? b2[x] : 0.f;
        sW3[x] = (x < H) ? W3[x] : 0.f;
    }
    __syncthreads();    // gih visible for A-fill

    // B copy for GEMM1: raw W1c^T chunk (shared across all CTAs)
    auto cp_B1 = [&](int ch, int buf) {
#pragma unroll
        for (int it = 0; it < 5; it++) {          // 160 rows x 8 segs = 1280
            const int x = tid + it * NT;
            const int n = x >> 3, seg = x & 7;
            CP16(smb + OFB[buf] + n * RA + seg * 16,
                 (const char*)(d_B1h + n * D + ch * 64) + seg * 16);
        }
        CP_COMMIT();
    };
    // A fill: A'[m][d] = gj[m][d] * gi[d] in half2, from preloaded gj regs
    auto ld_gj = [&](int ch, uint4* r) {
        r[0] = *(const uint4*)(d_gh + ajc0 * D + ch * 64 + aseg0 * 8);
        r[1] = *(const uint4*)(d_gh + ajc1 * D + ch * 64 + aseg1 * 8);
    };
    auto st_A = [&](int buf, int ch, const uint4* r) {
        const uint4 gi0 = *(const uint4*)(smc + OF_GIH + (ch * 64 + aseg0 * 8) * 2);
        *(uint4*)(smc + OFA[buf] + am0 * RA + aseg0 * 16) = hmul4(r[0], gi0);
        *(uint4*)(smc + OFA[buf] + am1 * RA + aseg1 * 16) = hmul4(r[1], gi0);
    };

    // ---- chunk 0: B via cp.async, A direct
    cp_B1(0, 0);
    {
        uint4 r0[2];
        ld_gj(0, r0);
        st_A(0, 0, r0);
    }

    // ---- h1pre = Agi + Agj (half, into sH1) — overlaps B0 copy
#pragma unroll
    for (int it = 0; it < 5; it++) {               // 64 rows x 20 groups of 8
        const int x = tid + it * NT;
        const int m = x / 20, grp = x % 20;
        const int jc = min(max(i - WIN + kbase + m, 0), N_SPANS - 1);
        const float4 ai0 = ((const float4*)(d_Agi + i * HP + grp * 8))[0];
        const float4 ai1 = ((const float4*)(d_Agi + i * HP + grp * 8))[1];
        const float4 aj0 = ((const float4*)(d_Agj + jc * HP + grp * 8))[0];
        const float4 aj1 = ((const float4*)(d_Agj + jc * HP + grp * 8))[1];
        uint4 o;
        o.x = pack2(ai0.x + aj0.x, ai0.y + aj0.y);
        o.y = pack2(ai0.z + aj0.z, ai0.w + aj0.w);
        o.z = pack2(ai1.x + aj1.x, ai1.y + aj1.y);
        o.w = pack2(ai1.z + aj1.z, ai1.w + aj1.w);
        *(uint4*)(smc + OF_H1 + m * RH + grp * 16) = o;
    }

    float acc[2][5][4];
#pragma unroll
    for (int ma = 0; ma < 2; ma++)
#pragma unroll
        for (int na = 0; na < 5; na++)
#pragma unroll
            for (int q = 0; q < 4; q++) acc[ma][na][q] = 0.f;

    auto mma_steps = [&](int abase, int bbase, int aks0, int nks, int astride) {
#pragma unroll 1
        for (int ks = 0; ks < nks; ks++) {
            uint32_t a[2][4];
#pragma unroll
            for (int ma = 0; ma < 2; ma++)
                ldm_x4(a[ma], smb + abase + (warp_m * 32 + ma * 16 + row_l) * astride + (aks0 + ks) * 32 + col_l);
            uint32_t b[5][2];
            {
                uint32_t t[4];
#pragma unroll
                for (int pr = 0; pr < 2; pr++) {
                    ldm_x4(t, smb + bbase + (warp_n * 40 + pr * 16 + row_l) * RA + ks * 32 + col_l);
                    b[pr * 2 + 0][0] = t[0]; b[pr * 2 + 0][1] = t[2];
                    b[pr * 2 + 1][0] = t[1]; b[pr * 2 + 1][1] = t[3];
                }
                ldm_x2(b[4], smb + bbase + (warp_n * 40 + 32 + rowB2l) * RA + ks * 32 + colB2l);
            }
#pragma unroll
            for (int ma = 0; ma < 2; ma++)
#pragma unroll
                for (int na = 0; na < 5; na++) mma_f16(acc[ma][na], a[ma], b[na]);
        }
    };

    // stage a GEMM2 W2 chunk
    auto cp_chunk2 = [&](int ch, int buf) {
        const int nseg = (ch == 2) ? 4 : 8;
        const int items = HP * nseg;
#pragma unroll
        for (int it = 0; it < 5; it++) {
            const int x = tid + it * NT;
            if (x < items) {
                const int n = x / nseg, seg = x % nseg;
                CP16(smb + OFB[buf] + n * RA + seg * 16,
                     (const char*)(d_B2h + n * HP + ch * 64) + seg * 16);
            }
        }
        CP_COMMIT();
    };

    // =================== GEMM1: 8 chunks, single-sync pipeline ==============
#pragma unroll 1
    for (int ch = 0; ch < 8; ch++) {
        const int cur = ch & 1;
        CP_WAIT0();              // B(ch) arrived
        __syncthreads();         // A(ch)/B(ch) visible; mma(ch-1) done
        uint4 rgj[2];
        if (ch < 7) { ld_gj(ch + 1, rgj); cp_B1(ch + 1, cur ^ 1); }
        else        cp_chunk2(0, 0);      // hoisted GEMM2 B chunk 0 (B0 idle)
        mma_steps(OFA[cur], OFB[cur], 0, 4, RA);
        if (ch < 7) st_A(cur ^ 1, ch + 1, rgj);
    }

    // ====== Epilogue 1: h1 = half(relu(acc + pre)) in place (per-warp cells)
#pragma unroll
    for (int ma = 0; ma < 2; ma++) {
        const int r0 = warp_m * 32 + ma * 16 + gq;
#pragma unroll
        for (int na = 0; na < 5; na++) {
            const int c0 = warp_n * 40 + na * 8 + tg * 2;
            uint32_t* p0 = (uint32_t*)(smc + OF_H1 + r0 * RH + c0 * 2);
            uint32_t* p1 = (uint32_t*)(smc + OF_H1 + (r0 + 8) * RH + c0 * 2);
            const float2 pre0 = __half22float2(*(__half2*)p0);
            const float2 pre1 = __half22float2(*(__half2*)p1);
            *p0 = pack2(fmaxf(acc[ma][na][0] + pre0.x, 0.f),
                        fmaxf(acc[ma][na][1] + pre0.y, 0.f));
            *p1 = pack2(fmaxf(acc[ma][na][2] + pre1.x, 0.f),
                        fmaxf(acc[ma][na][3] + pre1.y, 0.f));
        }
    }
#pragma unroll
    for (int ma = 0; ma < 2; ma++)
#pragma unroll
        for (int na = 0; na < 5; na++)
#pragma unroll
            for (int q = 0; q < 4; q++) acc[ma][na][q] = 0.f;

    CP_WAIT0();                  // W2 chunk 0 arrived
    __syncthreads();             // h1 visible to all warps

    // ========= GEMM2: 3 chunks (k64,k64,k32), single-sync handoffs ==========
#pragma unroll 1
    for (int ch = 0; ch < 3; ch++) {
        const int cur = ch & 1;
        if (ch < 2) cp_chunk2(ch + 1, cur ^ 1);
        mma_steps(OF_H1, OFB[cur], ch * 4, (ch < 2) ? 4 : 2, RH);
        if (ch < 2) { CP_WAIT0(); __syncthreads(); }
    }

    // ====== Epilogue 2: s[m] = sum_h relu(acc + b2[h]) * W3[h] ==============
    float part[4] = {0.f, 0.f, 0.f, 0.f};
#pragma unroll
    for (int ma = 0; ma < 2; ma++) {
#pragma unroll
        for (int na = 0; na < 5; na++) {
            const int c0 = warp_n * 40 + na * 8 + tg * 2;
            const float2 bb = *(const float2*)(sB2 + c0);
            const float2 ww = *(const float2*)(sW3 + c0);
            part[ma * 2 + 0] += fmaxf(acc[ma][na][0] + bb.x, 0.f) * ww.x
                              + fmaxf(acc[ma][na][1] + bb.y, 0.f) * ww.y;
            part[ma * 2 + 1] += fmaxf(acc[ma][na][2] + bb.x, 0.f) * ww.x
                              + fmaxf(acc[ma][na][3] + bb.y, 0.f) * ww.y;
        }
    }
#pragma unroll
    for (int q = 0; q < 4; q++) {
        part[q] += __shfl_xor_sync(0xffffffffu, part[q], 1);
        part[q] += __shfl_xor_sync(0xffffffffu, part[q], 2);
    }
    if (tg == 0) {
        const int r0 = warp_m * 32 + gq;
        sRD[warp_n * 64 + r0 +  0] = part[0];
        sRD[warp_n * 64 + r0 +  8] = part[1];
        sRD[warp_n * 64 + r0 + 16] = part[2];
        sRD[warp_n * 64 + r0 + 24] = part[3];
    }
    __syncthreads();

    if (tid < 64) {
        const int m = tid;
        const int k = kbase + m;
        const float s = sRD[m] + sRD[64 + m] + sRD[128 + m] + sRD[192 + m] + b3[0];
        if (k < WIN) {
            const int j = i - WIN + k;
            out[i * OUTW + k] = (j >= 0) ? (sm[i] + sm[j] + s) : 0.f;
        } else if (k == WIN) {
            out[i * OUTW + WIN] = 0.f;
        }
    }
}

// ---------------------------------------------------------------------------
extern "C" void kernel_launch(void* const* d_in, const int* in_sizes, int n_in,
                              void* d_out, int out_size) {
    const float* g  = (const float*)d_in[0];
    const float* sm = (const float*)d_in[1];
    const float* W1 = (const float*)d_in[2];
    const float* b1 = (const float*)d_in[3];
    const float* W2 = (const float*)d_in[4];
    const float* b2 = (const float*)d_in[5];
    const float* W3 = (const float*)d_in[6];
    const float* b3 = (const float*)d_in[7];
    float* out = (float*)d_out;

    cudaFuncSetAttribute(pair_mma_kernel, cudaFuncAttributeMaxDynamicSharedMemorySize,
                         SMEM_BYTES);

    proj_kernel<<<N_SPANS, 160>>>(g, W1, b1);
    prep_fused_kernel<<<N_SPANS + HP, 512>>>(g, W1, W2);
    pair_mma_kernel<<<4 * N_SPANS, NT, SMEM_BYTES>>>(sm, W3, b2, b3, out);
}